// round 1
// baseline (speedup 1.0000x reference)
#include <cuda_runtime.h>

#define NB 4
#define NS 2048
#define NE 128
#define NH 16
#define ND 8
#define NBH (NB * NH)

// Scratch (static device globals — no allocation allowed)
__device__ float g_q[NBH * NS * ND];       // [b*H+h][s][d], 2 MB
__device__ float g_attn[NB * NS * NE];     // [b][s][e],     4 MB

// Fast exp: argument bounded to [-2.83, 2.83] by construction (|q_i|<=1).
// y = x*log2(e); n = rn(y) via 2^23 trick; 2^f degree-5 poly; scale by 2^n
// through exponent-bit add. Max rel err ~2.4e-6.
__device__ __forceinline__ float fexp(float x) {
    float y = x * 1.4426950408889634f;
    float t = y + 12582912.0f;                 // 1.5 * 2^23
    int   n = __float_as_int(t) << 23;         // == rn(y) << 23 (see note)
    float f = y - (t - 12582912.0f);           // f in [-0.5, 0.5]
    float p =        1.3333558146e-3f;
    p = fmaf(p, f,   9.6181291076e-3f);
    p = fmaf(p, f,   5.5504108664e-2f);
    p = fmaf(p, f,   2.4022650696e-1f);
    p = fmaf(p, f,   6.9314718056e-1f);
    p = fmaf(p, f,   1.0f);
    return __int_as_float(__float_as_int(p) + n);
}

// ---------------------------------------------------------------------------
// Kernel A: q[b,h,s,:] = cumprod(cos(x[b,s,h*8+:] + theta))
// One thread per (b,h,s) row; 2x float4 in, 2x float4 out.
// ---------------------------------------------------------------------------
__global__ void __launch_bounds__(256) qgen_kernel(const float* __restrict__ x,
                                                   const float* __restrict__ theta) {
    int r = blockIdx.x * blockDim.x + threadIdx.x;   // r = (b*NH + h)*NS + s
    if (r >= NBH * NS) return;
    int s  = r & (NS - 1);
    int bh = r >> 11;               // NS = 2048 = 2^11
    int h  = bh & (NH - 1);
    int b  = bh >> 4;               // NH = 16

    const float4* xp = (const float4*)(x + ((size_t)(b * NS + s) * NE + h * ND));
    float4 x0 = xp[0], x1 = xp[1];

    float4 o0, o1;
    float p;
    p  = cosf(x0.x + theta[0]);  o0.x = p;
    p *= cosf(x0.y + theta[1]);  o0.y = p;
    p *= cosf(x0.z + theta[2]);  o0.z = p;
    p *= cosf(x0.w + theta[3]);  o0.w = p;
    p *= cosf(x1.x + theta[4]);  o1.x = p;
    p *= cosf(x1.y + theta[5]);  o1.y = p;
    p *= cosf(x1.z + theta[6]);  o1.z = p;
    p *= cosf(x1.w + theta[7]);  o1.w = p;

    float4* qp = (float4*)(g_q + (size_t)r * ND);
    qp[0] = o0;
    qp[1] = o1;
}

// ---------------------------------------------------------------------------
// Kernel B: attention for one (b,h) per blockIdx.x, query slice per blockIdx.y.
// K (= q) for the whole head lives in SMEM (64 KB) + mask row (8 KB).
// One query per thread; single-pass softmax (scores bounded => no max needed).
// ---------------------------------------------------------------------------
__global__ void __launch_bounds__(256) attn_kernel(const int* __restrict__ mask) {
    extern __shared__ float sm[];
    float4* sK = (float4*)sm;                 // NS*2 float4 = 64 KB
    float*  sM = sm + NS * ND;                // NS floats  =  8 KB

    int bh = blockIdx.x;
    int b  = bh >> 4;
    int h  = bh & (NH - 1);

    const float4* gk = (const float4*)(g_q + (size_t)bh * NS * ND);
    for (int i = threadIdx.x; i < NS * 2; i += 256) sK[i] = gk[i];
    const int* mrow = mask + b * NS;
    for (int i = threadIdx.x; i < NS; i += 256) sM[i] = (float)mrow[i];
    __syncthreads();

    int qi = blockIdx.y * 256 + threadIdx.x;  // query index in [0, NS)

    float4 q0 = sK[qi * 2], q1 = sK[qi * 2 + 1];
    const float sc = 0.35355339059327373f;    // 1/sqrt(8), folded into q
    q0.x *= sc; q0.y *= sc; q0.z *= sc; q0.w *= sc;
    q1.x *= sc; q1.y *= sc; q1.z *= sc; q1.w *= sc;

    float a0 = 0.f, a1 = 0.f, a2 = 0.f, a3 = 0.f;
    float a4 = 0.f, a5 = 0.f, a6 = 0.f, a7 = 0.f;
    float den = 0.f;

#pragma unroll 4
    for (int t = 0; t < NS; ++t) {
        float4 k0 = sK[2 * t];
        float4 k1 = sK[2 * t + 1];
        float s = q0.x * k0.x;
        s = fmaf(q0.y, k0.y, s);
        s = fmaf(q0.z, k0.z, s);
        s = fmaf(q0.w, k0.w, s);
        s = fmaf(q1.x, k1.x, s);
        s = fmaf(q1.y, k1.y, s);
        s = fmaf(q1.z, k1.z, s);
        s = fmaf(q1.w, k1.w, s);
        float e = fexp(s) * sM[t];
        den += e;
        a0 = fmaf(e, k0.x, a0);
        a1 = fmaf(e, k0.y, a1);
        a2 = fmaf(e, k0.z, a2);
        a3 = fmaf(e, k0.w, a3);
        a4 = fmaf(e, k1.x, a4);
        a5 = fmaf(e, k1.y, a5);
        a6 = fmaf(e, k1.z, a6);
        a7 = fmaf(e, k1.w, a7);
    }

    float inv = __fdividef(1.0f, fmaxf(den, 1e-30f));
    float4 r0 = make_float4(a0 * inv, a1 * inv, a2 * inv, a3 * inv);
    float4 r1 = make_float4(a4 * inv, a5 * inv, a6 * inv, a7 * inv);

    float4* op = (float4*)(g_attn + ((size_t)(b * NS + qi) * NE + h * ND));
    op[0] = r0;
    op[1] = r1;
}

// ---------------------------------------------------------------------------
// Kernel C: out[r, e] = sum_f attn[r, f] * w_out[e, f]
// w_out transposed into padded SMEM (stride 132 floats: float4-aligned,
// conflict-free). Each warp: 8 rows; each lane: 4 output columns via float4.
// ---------------------------------------------------------------------------
__global__ void __launch_bounds__(256) out_kernel(const float* __restrict__ w,
                                                  float* __restrict__ out) {
    extern __shared__ float sW[];   // [128][132] floats (padded transpose)
    for (int i = threadIdx.x; i < NE * NE; i += 256) {
        int e = i >> 7;
        int f = i & 127;
        sW[f * 132 + e] = w[i];
    }
    __syncthreads();

    int warp = threadIdx.x >> 5;
    int lane = threadIdx.x & 31;
    int rbase = blockIdx.x * 64 + warp * 8;

    for (int k = 0; k < 8; ++k) {
        int r = rbase + k;
        const float4* arow = (const float4*)(g_attn + (size_t)r * NE);
        float4 acc = make_float4(0.f, 0.f, 0.f, 0.f);
#pragma unroll 4
        for (int fi = 0; fi < 32; ++fi) {
            float4 a4 = arow[fi];     // same addr across warp -> broadcast LDG
            int f = fi * 4;
            float4 w0 = *(const float4*)&sW[(f + 0) * 132 + lane * 4];
            acc.x = fmaf(a4.x, w0.x, acc.x);
            acc.y = fmaf(a4.x, w0.y, acc.y);
            acc.z = fmaf(a4.x, w0.z, acc.z);
            acc.w = fmaf(a4.x, w0.w, acc.w);
            float4 w1 = *(const float4*)&sW[(f + 1) * 132 + lane * 4];
            acc.x = fmaf(a4.y, w1.x, acc.x);
            acc.y = fmaf(a4.y, w1.y, acc.y);
            acc.z = fmaf(a4.y, w1.z, acc.z);
            acc.w = fmaf(a4.y, w1.w, acc.w);
            float4 w2 = *(const float4*)&sW[(f + 2) * 132 + lane * 4];
            acc.x = fmaf(a4.z, w2.x, acc.x);
            acc.y = fmaf(a4.z, w2.y, acc.y);
            acc.z = fmaf(a4.z, w2.z, acc.z);
            acc.w = fmaf(a4.z, w2.w, acc.w);
            float4 w3 = *(const float4*)&sW[(f + 3) * 132 + lane * 4];
            acc.x = fmaf(a4.w, w3.x, acc.x);
            acc.y = fmaf(a4.w, w3.y, acc.y);
            acc.z = fmaf(a4.w, w3.z, acc.z);
            acc.w = fmaf(a4.w, w3.w, acc.w);
        }
        *(float4*)(out + (size_t)r * NE + lane * 4) = acc;
    }
}

// ---------------------------------------------------------------------------
extern "C" void kernel_launch(void* const* d_in, const int* in_sizes, int n_in,
                              void* d_out, int out_size) {
    const float* x     = (const float*)d_in[0];
    const float* theta = (const float*)d_in[1];
    const float* w     = (const float*)d_in[2];
    const int*   mask  = (const int*)d_in[3];
    float*       out   = (float*)d_out;

    qgen_kernel<<<(NBH * NS) / 256, 256>>>(x, theta);

    int smB = NS * ND * 4 + NS * 4;   // 64 KB K + 8 KB mask = 73728 B
    cudaFuncSetAttribute(attn_kernel, cudaFuncAttributeMaxDynamicSharedMemorySize, smB);
    attn_kernel<<<dim3(NBH, NS / 256), 256, smB>>>(mask);

    int smC = 128 * 132 * 4;          // 67584 B padded transposed w_out
    cudaFuncSetAttribute(out_kernel, cudaFuncAttributeMaxDynamicSharedMemorySize, smC);
    out_kernel<<<(NB * NS) / 64, 256, smC>>>(w, out);
}

// round 2
// speedup vs baseline: 1.2910x; 1.2910x over previous
#include <cuda_runtime.h>

#define NB 4
#define NS 2048
#define NE 128
#define NH 16
#define ND 8
#define NBH (NB * NH)

// Scratch (static device globals — no allocation allowed)
__device__ float g_q[NBH * NS * ND];       // [b*H+h][s][d], 2 MB
__device__ float g_attn[NB * NS * NE];     // [b][s][e],     4 MB

// ---- packed f32x2 helpers (Blackwell FMA-pipe packed ops) ----
typedef unsigned long long f2;
__device__ __forceinline__ f2 pack2(float lo, float hi) {
    f2 r; asm("mov.b64 %0,{%1,%2};" : "=l"(r) : "f"(lo), "f"(hi)); return r;
}
__device__ __forceinline__ void unpack2(f2 v, float& lo, float& hi) {
    asm("mov.b64 {%0,%1},%2;" : "=f"(lo), "=f"(hi) : "l"(v));
}
__device__ __forceinline__ f2 fma2(f2 a, f2 b, f2 c) {
    f2 r; asm("fma.rn.f32x2 %0,%1,%2,%3;" : "=l"(r) : "l"(a), "l"(b), "l"(c)); return r;
}
__device__ __forceinline__ f2 mul2(f2 a, f2 b) {
    f2 r; asm("mul.rn.f32x2 %0,%1,%2;" : "=l"(r) : "l"(a), "l"(b)); return r;
}
__device__ __forceinline__ f2 add2(f2 a, f2 b) {
    f2 r; asm("add.rn.f32x2 %0,%1,%2;" : "=l"(r) : "l"(a), "l"(b)); return r;
}
__device__ __forceinline__ float ex2f(float x) {
    float r; asm("ex2.approx.f32 %0,%1;" : "=f"(r) : "f"(x)); return r;
}

// ---------------------------------------------------------------------------
// Kernel A: q[b,h,s,:] = cumprod(cos(x[b,s,h*8+:] + theta))
// ---------------------------------------------------------------------------
__global__ void __launch_bounds__(256) qgen_kernel(const float* __restrict__ x,
                                                   const float* __restrict__ theta) {
    int r = blockIdx.x * blockDim.x + threadIdx.x;   // r = (b*NH + h)*NS + s
    if (r >= NBH * NS) return;
    int s  = r & (NS - 1);
    int bh = r >> 11;
    int h  = bh & (NH - 1);
    int b  = bh >> 4;

    const float4* xp = (const float4*)(x + ((size_t)(b * NS + s) * NE + h * ND));
    float4 x0 = xp[0], x1 = xp[1];

    float4 o0, o1;
    float p;
    p  = cosf(x0.x + theta[0]);  o0.x = p;
    p *= cosf(x0.y + theta[1]);  o0.y = p;
    p *= cosf(x0.z + theta[2]);  o0.z = p;
    p *= cosf(x0.w + theta[3]);  o0.w = p;
    p *= cosf(x1.x + theta[4]);  o1.x = p;
    p *= cosf(x1.y + theta[5]);  o1.y = p;
    p *= cosf(x1.z + theta[6]);  o1.z = p;
    p *= cosf(x1.w + theta[7]);  o1.w = p;

    float4* qp = (float4*)(g_q + (size_t)r * ND);
    qp[0] = o0;
    qp[1] = o1;
}

// ---------------------------------------------------------------------------
// Kernel B: attention. One (b,h) per blockIdx.x, 512-query slice per blockIdx.y.
// K (=q) for the head in SMEM (64 KB) + additive mask bias (8 KB).
// TWO queries per thread, packed into f32x2 lanes:
//   - dot product: 8 packed FMAs produce both scores (no horizontal reduce)
//   - exp via MUFU ex2.approx (argument pre-scaled by log2(e)/sqrt(8) folded
//     into q; mask folded in as additive bias)
//   - PV accumulation: 8 packed FMAs reuse the same {k_d,k_d} packs (ALU pipe)
// 18 packed FMA-pipe instrs per (key, 2 queries) => ~9 per key-query.
// ---------------------------------------------------------------------------
__global__ void __launch_bounds__(256) attn_kernel(const int* __restrict__ mask) {
    extern __shared__ float smem[];
    float4* sK  = (float4*)smem;              // NS*2 float4 = 64 KB
    float*  sMB = smem + NS * ND;             // NS floats   =  8 KB

    int bh = blockIdx.x;
    int b  = bh >> 4;
    int h  = bh & (NH - 1);

    const float4* gk = (const float4*)(g_q + (size_t)bh * NS * ND);
    for (int i = threadIdx.x; i < NS * 2; i += 256) sK[i] = gk[i];
    const int* mrow = mask + b * NS;
    for (int i = threadIdx.x; i < NS; i += 256) sMB[i] = mrow[i] ? 0.0f : -1.0e9f;
    __syncthreads();

    int qA = blockIdx.y * 512 + threadIdx.x;
    int qB = qA + 256;

    float4 A0 = sK[2 * qA], A1 = sK[2 * qA + 1];
    float4 B0 = sK[2 * qB], B1 = sK[2 * qB + 1];
    const float CL = 0.51010205144336435f;    // log2(e) / sqrt(8)

    f2 qp[8];
    qp[0] = pack2(A0.x * CL, B0.x * CL);
    qp[1] = pack2(A0.y * CL, B0.y * CL);
    qp[2] = pack2(A0.z * CL, B0.z * CL);
    qp[3] = pack2(A0.w * CL, B0.w * CL);
    qp[4] = pack2(A1.x * CL, B1.x * CL);
    qp[5] = pack2(A1.y * CL, B1.y * CL);
    qp[6] = pack2(A1.z * CL, B1.z * CL);
    qp[7] = pack2(A1.w * CL, B1.w * CL);

    f2 acc[8];
#pragma unroll
    for (int d = 0; d < 8; ++d) acc[d] = 0ULL;
    f2 den = 0ULL;

#pragma unroll 2
    for (int t = 0; t < NS; ++t) {
        float4 k0 = sK[2 * t];
        float4 k1 = sK[2 * t + 1];
        float  mb = sMB[t];

        f2 kk[8];
        kk[0] = pack2(k0.x, k0.x);
        kk[1] = pack2(k0.y, k0.y);
        kk[2] = pack2(k0.z, k0.z);
        kk[3] = pack2(k0.w, k0.w);
        kk[4] = pack2(k1.x, k1.x);
        kk[5] = pack2(k1.y, k1.y);
        kk[6] = pack2(k1.z, k1.z);
        kk[7] = pack2(k1.w, k1.w);

        f2 s2 = mul2(qp[0], kk[0]);
#pragma unroll
        for (int d = 1; d < 8; ++d) s2 = fma2(qp[d], kk[d], s2);

        f2 y2 = add2(s2, pack2(mb, mb));      // masked-out keys -> -1e9 -> e=0
        float y0, y1;
        unpack2(y2, y0, y1);
        f2 ee = pack2(ex2f(y0), ex2f(y1));    // exp on MUFU pipe

        den = add2(den, ee);
#pragma unroll
        for (int d = 0; d < 8; ++d) acc[d] = fma2(ee, kk[d], acc[d]);
    }

    float d0, d1;
    unpack2(den, d0, d1);
    float i0 = __fdividef(1.0f, fmaxf(d0, 1e-30f));
    float i1 = __fdividef(1.0f, fmaxf(d1, 1e-30f));

    float rA[8], rB[8];
#pragma unroll
    for (int d = 0; d < 8; ++d) {
        float lo, hi;
        unpack2(acc[d], lo, hi);
        rA[d] = lo * i0;
        rB[d] = hi * i1;
    }

    float4* oA = (float4*)(g_attn + ((size_t)(b * NS + qA) * NE + h * ND));
    oA[0] = make_float4(rA[0], rA[1], rA[2], rA[3]);
    oA[1] = make_float4(rA[4], rA[5], rA[6], rA[7]);
    float4* oB = (float4*)(g_attn + ((size_t)(b * NS + qB) * NE + h * ND));
    oB[0] = make_float4(rB[0], rB[1], rB[2], rB[3]);
    oB[1] = make_float4(rB[4], rB[5], rB[6], rB[7]);
}

// ---------------------------------------------------------------------------
// Kernel C: out[r, e] = sum_f attn[r, f] * w_out[e, f]
// ---------------------------------------------------------------------------
__global__ void __launch_bounds__(256) out_kernel(const float* __restrict__ w,
                                                  float* __restrict__ out) {
    extern __shared__ float sW[];   // [128][132] floats (padded transpose)
    for (int i = threadIdx.x; i < NE * NE; i += 256) {
        int e = i >> 7;
        int f = i & 127;
        sW[f * 132 + e] = w[i];
    }
    __syncthreads();

    int warp = threadIdx.x >> 5;
    int lane = threadIdx.x & 31;
    int rbase = blockIdx.x * 64 + warp * 8;

    for (int k = 0; k < 8; ++k) {
        int r = rbase + k;
        const float4* arow = (const float4*)(g_attn + (size_t)r * NE);
        float4 acc = make_float4(0.f, 0.f, 0.f, 0.f);
#pragma unroll 4
        for (int fi = 0; fi < 32; ++fi) {
            float4 a4 = arow[fi];
            int f = fi * 4;
            float4 w0 = *(const float4*)&sW[(f + 0) * 132 + lane * 4];
            acc.x = fmaf(a4.x, w0.x, acc.x);
            acc.y = fmaf(a4.x, w0.y, acc.y);
            acc.z = fmaf(a4.x, w0.z, acc.z);
            acc.w = fmaf(a4.x, w0.w, acc.w);
            float4 w1 = *(const float4*)&sW[(f + 1) * 132 + lane * 4];
            acc.x = fmaf(a4.y, w1.x, acc.x);
            acc.y = fmaf(a4.y, w1.y, acc.y);
            acc.z = fmaf(a4.y, w1.z, acc.z);
            acc.w = fmaf(a4.y, w1.w, acc.w);
            float4 w2 = *(const float4*)&sW[(f + 2) * 132 + lane * 4];
            acc.x = fmaf(a4.z, w2.x, acc.x);
            acc.y = fmaf(a4.z, w2.y, acc.y);
            acc.z = fmaf(a4.z, w2.z, acc.z);
            acc.w = fmaf(a4.z, w2.w, acc.w);
            float4 w3 = *(const float4*)&sW[(f + 3) * 132 + lane * 4];
            acc.x = fmaf(a4.w, w3.x, acc.x);
            acc.y = fmaf(a4.w, w3.y, acc.y);
            acc.z = fmaf(a4.w, w3.z, acc.z);
            acc.w = fmaf(a4.w, w3.w, acc.w);
        }
        *(float4*)(out + (size_t)r * NE + lane * 4) = acc;
    }
}

// ---------------------------------------------------------------------------
extern "C" void kernel_launch(void* const* d_in, const int* in_sizes, int n_in,
                              void* d_out, int out_size) {
    const float* x     = (const float*)d_in[0];
    const float* theta = (const float*)d_in[1];
    const float* w     = (const float*)d_in[2];
    const int*   mask  = (const int*)d_in[3];
    float*       out   = (float*)d_out;

    qgen_kernel<<<(NBH * NS) / 256, 256>>>(x, theta);

    int smB = NS * ND * 4 + NS * 4;   // 64 KB K + 8 KB mask bias = 73728 B
    cudaFuncSetAttribute(attn_kernel, cudaFuncAttributeMaxDynamicSharedMemorySize, smB);
    attn_kernel<<<dim3(NBH, NS / 512), 256, smB>>>(mask);

    int smC = 128 * 132 * 4;          // 67584 B padded transposed w_out
    cudaFuncSetAttribute(out_kernel, cudaFuncAttributeMaxDynamicSharedMemorySize, smC);
    out_kernel<<<(NB * NS) / 64, 256, smC>>>(w, out);
}

// round 3
// speedup vs baseline: 1.3632x; 1.0559x over previous
#include <cuda_runtime.h>

#define NB 4
#define NS 2048
#define NE 128
#define NH 16
#define ND 8
#define NBH (NB * NH)

// Scratch (static device globals — no allocation allowed)
__device__ float g_q [NBH * NS * ND];      // [bh][s][d] normal layout, 2 MB
__device__ float g_qp[NBH * NS * ND];      // [bh][s/2][d][s%2] pair-packed, 2 MB
__device__ float g_attn[NB * NS * NE];     // [b][s][e], 4 MB

// ---- packed f32x2 helpers ----
typedef unsigned long long f2;
__device__ __forceinline__ f2 pack2(float lo, float hi) {
    f2 r; asm("mov.b64 %0,{%1,%2};" : "=l"(r) : "f"(lo), "f"(hi)); return r;
}
__device__ __forceinline__ void unpack2(f2 v, float& lo, float& hi) {
    asm("mov.b64 {%0,%1},%2;" : "=f"(lo), "=f"(hi) : "l"(v));
}
__device__ __forceinline__ f2 fma2(f2 a, f2 b, f2 c) {
    f2 r; asm("fma.rn.f32x2 %0,%1,%2,%3;" : "=l"(r) : "l"(a), "l"(b), "l"(c)); return r;
}
__device__ __forceinline__ f2 add2(f2 a, f2 b) {
    f2 r; asm("add.rn.f32x2 %0,%1,%2;" : "=l"(r) : "l"(a), "l"(b)); return r;
}
__device__ __forceinline__ float ex2f(float x) {
    float r; asm("ex2.approx.f32 %0,%1;" : "=f"(r) : "f"(x)); return r;
}

// ---------------------------------------------------------------------------
// Kernel A: q = cumprod(cos(x+theta)); writes normal AND pair-packed layouts.
// ---------------------------------------------------------------------------
__global__ void __launch_bounds__(256) qgen_kernel(const float* __restrict__ x,
                                                   const float* __restrict__ theta) {
    int r = blockIdx.x * blockDim.x + threadIdx.x;   // r = bh*NS + s
    if (r >= NBH * NS) return;
    int s  = r & (NS - 1);
    int bh = r >> 11;
    int h  = bh & (NH - 1);
    int b  = bh >> 4;

    const float4* xp = (const float4*)(x + ((size_t)(b * NS + s) * NE + h * ND));
    float4 x0 = xp[0], x1 = xp[1];

    float v[8];
    float p;
    p  = cosf(x0.x + theta[0]);  v[0] = p;
    p *= cosf(x0.y + theta[1]);  v[1] = p;
    p *= cosf(x0.z + theta[2]);  v[2] = p;
    p *= cosf(x0.w + theta[3]);  v[3] = p;
    p *= cosf(x1.x + theta[4]);  v[4] = p;
    p *= cosf(x1.y + theta[5]);  v[5] = p;
    p *= cosf(x1.z + theta[6]);  v[6] = p;
    p *= cosf(x1.w + theta[7]);  v[7] = p;

    float4* qp = (float4*)(g_q + (size_t)r * ND);
    qp[0] = make_float4(v[0], v[1], v[2], v[3]);
    qp[1] = make_float4(v[4], v[5], v[6], v[7]);

    // pair-packed: g_qp[bh*NS*ND + (s>>1)*16 + d*2 + (s&1)]
    float* pp = g_qp + (size_t)bh * NS * ND + (size_t)(s >> 1) * 16 + (s & 1);
#pragma unroll
    for (int d = 0; d < 8; ++d) pp[2 * d] = v[d];
}

// ---------------------------------------------------------------------------
// Kernel B: attention. One (b,h) per blockIdx.x, 512 queries per blockIdx.y.
// SMEM: pair-packed K (64 KB) + pair-packed mask bias as f2 (8 KB).
// 2 queries/thread, 2 keys/iter, all f32x2, zero in-loop packing MOVs.
// ---------------------------------------------------------------------------
__global__ void __launch_bounds__(256) attn_kernel(const int* __restrict__ mask) {
    extern __shared__ float smem[];
    float* sKP = smem;                       // 1024 pairs * 16 floats = 64 KB
    f2*    sMB = (f2*)(smem + NS * ND);      // 1024 f2 = 8 KB

    int bh = blockIdx.x;
    int b  = bh >> 4;
    int h  = bh & (NH - 1);

    const float4* gk = (const float4*)(g_qp + (size_t)bh * NS * ND);
    float4* sk4 = (float4*)sKP;
    for (int i = threadIdx.x; i < NS * 2; i += 256) sk4[i] = gk[i];
    const int* mrow = mask + b * NS;
    for (int i = threadIdx.x; i < NS / 2; i += 256) {
        float m0 = mrow[2 * i]     ? 0.0f : -1.0e9f;
        float m1 = mrow[2 * i + 1] ? 0.0f : -1.0e9f;
        sMB[i] = pack2(m0, m1);
    }
    __syncthreads();

    int qA = blockIdx.y * 512 + threadIdx.x;
    int qB = qA + 256;

    // load own queries from normal layout
    const float4* gq = (const float4*)(g_q + (size_t)bh * NS * ND);
    float4 A0 = gq[2 * qA], A1 = gq[2 * qA + 1];
    float4 B0 = gq[2 * qB], B1 = gq[2 * qB + 1];
    const float CL = 0.51010205144336435f;   // log2(e) / sqrt(8)

    f2 qA2[8], qB2[8];
    qA2[0] = pack2(A0.x * CL, A0.x * CL);  qB2[0] = pack2(B0.x * CL, B0.x * CL);
    qA2[1] = pack2(A0.y * CL, A0.y * CL);  qB2[1] = pack2(B0.y * CL, B0.y * CL);
    qA2[2] = pack2(A0.z * CL, A0.z * CL);  qB2[2] = pack2(B0.z * CL, B0.z * CL);
    qA2[3] = pack2(A0.w * CL, A0.w * CL);  qB2[3] = pack2(B0.w * CL, B0.w * CL);
    qA2[4] = pack2(A1.x * CL, A1.x * CL);  qB2[4] = pack2(B1.x * CL, B1.x * CL);
    qA2[5] = pack2(A1.y * CL, A1.y * CL);  qB2[5] = pack2(B1.y * CL, B1.y * CL);
    qA2[6] = pack2(A1.z * CL, A1.z * CL);  qB2[6] = pack2(B1.z * CL, B1.z * CL);
    qA2[7] = pack2(A1.w * CL, A1.w * CL);  qB2[7] = pack2(B1.w * CL, B1.w * CL);

    f2 accA[8], accB[8];
#pragma unroll
    for (int d = 0; d < 8; ++d) { accA[d] = 0ULL; accB[d] = 0ULL; }
    f2 denA = 0ULL, denB = 0ULL;

    const f2* kp = (const f2*)sKP;
#pragma unroll 2
    for (int p = 0; p < NS / 2; ++p) {
        f2 kk[8];
#pragma unroll
        for (int d = 0; d < 8; ++d) kk[d] = kp[p * 8 + d];   // 4x LDS.128
        f2 mb2 = sMB[p];                                     // 1x LDS.64

        f2 sA = fma2(qA2[0], kk[0], mb2);                    // bias as FMA init
        f2 sB = fma2(qB2[0], kk[0], mb2);
#pragma unroll
        for (int d = 1; d < 8; ++d) {
            sA = fma2(qA2[d], kk[d], sA);
            sB = fma2(qB2[d], kk[d], sB);
        }

        float a0, a1, b0, b1;
        unpack2(sA, a0, a1);
        unpack2(sB, b0, b1);
        f2 eeA = pack2(ex2f(a0), ex2f(a1));
        f2 eeB = pack2(ex2f(b0), ex2f(b1));

        denA = add2(denA, eeA);
        denB = add2(denB, eeB);
#pragma unroll
        for (int d = 0; d < 8; ++d) {
            accA[d] = fma2(eeA, kk[d], accA[d]);
            accB[d] = fma2(eeB, kk[d], accB[d]);
        }
    }

    float dA0, dA1, dB0, dB1;
    unpack2(denA, dA0, dA1);
    unpack2(denB, dB0, dB1);
    float iA = __fdividef(1.0f, fmaxf(dA0 + dA1, 1e-30f));
    float iB = __fdividef(1.0f, fmaxf(dB0 + dB1, 1e-30f));

    float rA[8], rB[8];
#pragma unroll
    for (int d = 0; d < 8; ++d) {
        float lo, hi;
        unpack2(accA[d], lo, hi);  rA[d] = (lo + hi) * iA;
        unpack2(accB[d], lo, hi);  rB[d] = (lo + hi) * iB;
    }

    float4* oA = (float4*)(g_attn + ((size_t)(b * NS + qA) * NE + h * ND));
    oA[0] = make_float4(rA[0], rA[1], rA[2], rA[3]);
    oA[1] = make_float4(rA[4], rA[5], rA[6], rA[7]);
    float4* oB = (float4*)(g_attn + ((size_t)(b * NS + qB) * NE + h * ND));
    oB[0] = make_float4(rB[0], rB[1], rB[2], rB[3]);
    oB[1] = make_float4(rB[4], rB[5], rB[6], rB[7]);
}

// ---------------------------------------------------------------------------
// Kernel C: out[r, e] = sum_f attn[r, f] * w_out[e, f]
// ---------------------------------------------------------------------------
__global__ void __launch_bounds__(256) out_kernel(const float* __restrict__ w,
                                                  float* __restrict__ out) {
    extern __shared__ float sW[];   // [128][132] floats (padded transpose)
    for (int i = threadIdx.x; i < NE * NE; i += 256) {
        int e = i >> 7;
        int f = i & 127;
        sW[f * 132 + e] = w[i];
    }
    __syncthreads();

    int warp = threadIdx.x >> 5;
    int lane = threadIdx.x & 31;
    int rbase = blockIdx.x * 64 + warp * 8;

    for (int k = 0; k < 8; ++k) {
        int r = rbase + k;
        const float4* arow = (const float4*)(g_attn + (size_t)r * NE);
        float4 acc = make_float4(0.f, 0.f, 0.f, 0.f);
#pragma unroll 4
        for (int fi = 0; fi < 32; ++fi) {
            float4 a4 = arow[fi];
            int f = fi * 4;
            float4 w0 = *(const float4*)&sW[(f + 0) * 132 + lane * 4];
            acc.x = fmaf(a4.x, w0.x, acc.x);
            acc.y = fmaf(a4.x, w0.y, acc.y);
            acc.z = fmaf(a4.x, w0.z, acc.z);
            acc.w = fmaf(a4.x, w0.w, acc.w);
            float4 w1 = *(const float4*)&sW[(f + 1) * 132 + lane * 4];
            acc.x = fmaf(a4.y, w1.x, acc.x);
            acc.y = fmaf(a4.y, w1.y, acc.y);
            acc.z = fmaf(a4.y, w1.z, acc.z);
            acc.w = fmaf(a4.y, w1.w, acc.w);
            float4 w2 = *(const float4*)&sW[(f + 2) * 132 + lane * 4];
            acc.x = fmaf(a4.z, w2.x, acc.x);
            acc.y = fmaf(a4.z, w2.y, acc.y);
            acc.z = fmaf(a4.z, w2.z, acc.z);
            acc.w = fmaf(a4.z, w2.w, acc.w);
            float4 w3 = *(const float4*)&sW[(f + 3) * 132 + lane * 4];
            acc.x = fmaf(a4.w, w3.x, acc.x);
            acc.y = fmaf(a4.w, w3.y, acc.y);
            acc.z = fmaf(a4.w, w3.z, acc.z);
            acc.w = fmaf(a4.w, w3.w, acc.w);
        }
        *(float4*)(out + (size_t)r * NE + lane * 4) = acc;
    }
}

// ---------------------------------------------------------------------------
extern "C" void kernel_launch(void* const* d_in, const int* in_sizes, int n_in,
                              void* d_out, int out_size) {
    const float* x     = (const float*)d_in[0];
    const float* theta = (const float*)d_in[1];
    const float* w     = (const float*)d_in[2];
    const int*   mask  = (const int*)d_in[3];
    float*       out   = (float*)d_out;

    qgen_kernel<<<(NBH * NS) / 256, 256>>>(x, theta);

    int smB = NS * ND * 4 + (NS / 2) * 8;   // 64 KB packed K + 8 KB mask f2
    cudaFuncSetAttribute(attn_kernel, cudaFuncAttributeMaxDynamicSharedMemorySize, smB);
    attn_kernel<<<dim3(NBH, NS / 512), 256, smB>>>(mask);

    int smC = 128 * 132 * 4;                // 67584 B padded transposed w_out
    cudaFuncSetAttribute(out_kernel, cudaFuncAttributeMaxDynamicSharedMemorySize, smC);
    out_kernel<<<(NB * NS) / 64, 256, smC>>>(w, out);
}

// round 5
// speedup vs baseline: 2.5003x; 1.8341x over previous
#include <cuda_runtime.h>
#include <cuda_fp16.h>
#include <cstdint>

#define NB 4
#define NS 2048
#define NE 128
#define NH 16
#define ND 8
#define NBH (NB * NH)

// Staged head data (written by qgen, read by attn)
__device__ uint32_t g_kh[NBH * NS * 4];    // fp16x2 hi pairs [bh][s][4], 2 MB
__device__ uint32_t g_kl[NBH * NS * 4];    // fp16x2 lo pairs,            2 MB
__device__ uint32_t g_vp[NBH * (NS/2) * 8];// half2{v[2p][n],v[2p+1][n]},  2 MB
__device__ float    g_attn[NB * NS * NE];  // [b][s][e],                  4 MB

__device__ __forceinline__ float ex2f(float x) {
    float r; asm("ex2.approx.f32 %0,%1;" : "=f"(r) : "f"(x)); return r;
}
__device__ __forceinline__ uint32_t cvt_f16x2(float hi, float lo) {
    uint32_t r; asm("cvt.rn.f16x2.f32 %0,%1,%2;" : "=r"(r) : "f"(hi), "f"(lo)); return r;
}
__device__ __forceinline__ void mma16816(float c[4],
                                         uint32_t a0, uint32_t a1, uint32_t a2, uint32_t a3,
                                         uint32_t b0, uint32_t b1) {
    asm volatile("mma.sync.aligned.m16n8k16.row.col.f32.f16.f16.f32 "
                 "{%0,%1,%2,%3},{%4,%5,%6,%7},{%8,%9},{%0,%1,%2,%3};"
                 : "+f"(c[0]), "+f"(c[1]), "+f"(c[2]), "+f"(c[3])
                 : "r"(a0), "r"(a1), "r"(a2), "r"(a3), "r"(b0), "r"(b1));
}

// ---------------------------------------------------------------------------
// Kernel A: q = cumprod(cos(x+theta)); emit fp16 hi/lo pairs + pair-packed V.
// ---------------------------------------------------------------------------
__global__ void __launch_bounds__(256) qgen_kernel(const float* __restrict__ x,
                                                   const float* __restrict__ theta) {
    int r = blockIdx.x * blockDim.x + threadIdx.x;   // r = bh*NS + s
    if (r >= NBH * NS) return;
    int s  = r & (NS - 1);
    int bh = r >> 11;
    int h  = bh & (NH - 1);
    int b  = bh >> 4;

    const float4* xp = (const float4*)(x + ((size_t)(b * NS + s) * NE + h * ND));
    float4 x0 = xp[0], x1 = xp[1];

    float v[8];
    float p;
    p  = cosf(x0.x + theta[0]);  v[0] = p;
    p *= cosf(x0.y + theta[1]);  v[1] = p;
    p *= cosf(x0.z + theta[2]);  v[2] = p;
    p *= cosf(x0.w + theta[3]);  v[3] = p;
    p *= cosf(x1.x + theta[4]);  v[4] = p;
    p *= cosf(x1.y + theta[5]);  v[5] = p;
    p *= cosf(x1.z + theta[6]);  v[6] = p;
    p *= cosf(x1.w + theta[7]);  v[7] = p;

    uint32_t hw[4], lw[4];
#pragma unroll
    for (int j = 0; j < 4; ++j) {
        float a0 = v[2 * j], a1 = v[2 * j + 1];
        __half h0 = __float2half_rn(a0), h1 = __float2half_rn(a1);
        __half l0 = __float2half_rn(a0 - __half2float(h0));
        __half l1 = __float2half_rn(a1 - __half2float(h1));
        hw[j] = (uint32_t)__half_as_ushort(h0) | ((uint32_t)__half_as_ushort(h1) << 16);
        lw[j] = (uint32_t)__half_as_ushort(l0) | ((uint32_t)__half_as_ushort(l1) << 16);
    }
    ((uint4*)g_kh)[r] = make_uint4(hw[0], hw[1], hw[2], hw[3]);
    ((uint4*)g_kl)[r] = make_uint4(lw[0], lw[1], lw[2], lw[3]);

    // pair-packed V: g_vp[bh][s/2][n] = half2{v_even[n], v_odd[n]}
    uint16_t* vp16 = (uint16_t*)g_vp;
    size_t base = (((size_t)bh * (NS / 2) + (s >> 1)) * 8) * 2 + (s & 1);
#pragma unroll
    for (int n = 0; n < 8; ++n)
        vp16[base + 2 * n] = __half_as_ushort(__float2half_rn(v[n]));
}

// ---------------------------------------------------------------------------
// Kernel B: HMMA flash attention. CTA = (head bh, 256-query tile).
// 8 warps x 32 queries. Scores exact via hi/lo split; P stays in registers.
// ---------------------------------------------------------------------------
__global__ void __launch_bounds__(256) attn_kernel(const int* __restrict__ mask) {
    extern __shared__ char smem[];
    uint32_t* sKh = (uint32_t*)smem;                    // 2048*4 u32 = 32 KB
    uint32_t* sKl = sKh + NS * 4;                       // 32 KB
    uint32_t* sVp = sKl + NS * 4;                       // 32 KB
    float2*   sB  = (float2*)(sVp + NS * 4);            //  8 KB

    int tid = threadIdx.x;
    int bh = blockIdx.x;
    int b  = bh >> 4;
    int h  = bh & (NH - 1);

    {   // stage K hi/lo + V pairs (uint4 copies) and mask bias
        const uint4* gh = (const uint4*)(g_kh + (size_t)bh * NS * 4);
        const uint4* gl = (const uint4*)(g_kl + (size_t)bh * NS * 4);
        const uint4* gv = (const uint4*)(g_vp + (size_t)bh * (NS / 2) * 8);
        uint4* sh4 = (uint4*)sKh;
        uint4* sl4 = (uint4*)sKl;
        uint4* sv4 = (uint4*)sVp;
        for (int i = tid; i < NS; i += 256) { sh4[i] = gh[i]; sl4[i] = gl[i]; sv4[i] = gv[i]; }
        const int* mrow = mask + b * NS;
        for (int i = tid; i < NS / 2; i += 256)
            sB[i] = make_float2(mrow[2 * i] ? 0.0f : -1.0e9f,
                                mrow[2 * i + 1] ? 0.0f : -1.0e9f);
    }
    __syncthreads();

    int warp = tid >> 5, lane = tid & 31;
    int r0 = lane >> 2, cp = lane & 3;
    int qw = blockIdx.y * 256 + warp * 32;              // warp's first query

    // A fragments for the two 16-query tiles: [qh | ql] in 16 K-columns
    uint32_t A0[4], A1[4];
    A0[0] = sKh[(qw + r0) * 4 + cp];      A0[1] = sKh[(qw + r0 + 8) * 4 + cp];
    A0[2] = sKl[(qw + r0) * 4 + cp];      A0[3] = sKl[(qw + r0 + 8) * 4 + cp];
    A1[0] = sKh[(qw + 16 + r0) * 4 + cp]; A1[1] = sKh[(qw + 24 + r0) * 4 + cp];
    A1[2] = sKl[(qw + 16 + r0) * 4 + cp]; A1[3] = sKl[(qw + 24 + r0) * 4 + cp];

    const float CL = 0.51010205144336435f;  // log2(e) / sqrt(8)

    float o0[4] = {0.f, 0.f, 0.f, 0.f};
    float o1[4] = {0.f, 0.f, 0.f, 0.f};
    float d00 = 0.f, d01 = 0.f, d10 = 0.f, d11 = 0.f;

#pragma unroll 2
    for (int kb = 0; kb < NS; kb += 16) {
        uint32_t pe0, pe1, pe2, pe3, po0, po1, po2, po3;
#pragma unroll
        for (int g = 0; g < 2; ++g) {
            int k8 = kb + g * 8;
            uint32_t bhreg = sKh[(k8 + r0) * 4 + cp];   // B frag key = k8 + (lane>>2)? no:
            // B fragment: n = lane>>2 (key within 8), k-pair = cp
            // (r0 == lane>>2, so reuse it as the key index)
            uint32_t blreg = sKl[(k8 + r0) * 4 + cp];
            float c0[4] = {0.f, 0.f, 0.f, 0.f};
            float c1[4] = {0.f, 0.f, 0.f, 0.f};
            mma16816(c0, A0[0], A0[1], A0[2], A0[3], bhreg, bhreg);
            mma16816(c0, A0[0], A0[1], A0[2], A0[3], blreg, blreg);
            mma16816(c1, A1[0], A1[1], A1[2], A1[3], bhreg, bhreg);
            mma16816(c1, A1[0], A1[1], A1[2], A1[3], blreg, blreg);

            float2 bia = sB[(k8 >> 1) + cp];
            float e0 = ex2f(fmaf(c0[0], CL, bia.x));
            float e1 = ex2f(fmaf(c0[1], CL, bia.y));
            float e2 = ex2f(fmaf(c0[2], CL, bia.x));
            float e3 = ex2f(fmaf(c0[3], CL, bia.y));
            d00 += e0 + e1;  d01 += e2 + e3;
            uint32_t p0 = cvt_f16x2(e1, e0);
            uint32_t p1 = cvt_f16x2(e3, e2);

            float f0 = ex2f(fmaf(c1[0], CL, bia.x));
            float f1 = ex2f(fmaf(c1[1], CL, bia.y));
            float f2 = ex2f(fmaf(c1[2], CL, bia.x));
            float f3 = ex2f(fmaf(c1[3], CL, bia.y));
            d10 += f0 + f1;  d11 += f2 + f3;
            uint32_t p2 = cvt_f16x2(f1, f0);
            uint32_t p3 = cvt_f16x2(f3, f2);

            if (g == 0) { pe0 = p0; pe1 = p1; pe2 = p2; pe3 = p3; }
            else        { po0 = p0; po1 = p1; po2 = p2; po3 = p3; }
        }
        // PV: A = P(16q x 16k), B = V(16k x 8n)
        uint32_t vb0 = sVp[((kb >> 1) + cp) * 8 + r0];
        uint32_t vb1 = sVp[((kb >> 1) + 4 + cp) * 8 + r0];
        mma16816(o0, pe0, pe1, po0, po1, vb0, vb1);
        mma16816(o1, pe2, pe3, po2, po3, vb0, vb1);
    }

    // reduce den across the quad (lanes sharing the same row)
    d00 += __shfl_xor_sync(0xffffffffu, d00, 1); d00 += __shfl_xor_sync(0xffffffffu, d00, 2);
    d01 += __shfl_xor_sync(0xffffffffu, d01, 1); d01 += __shfl_xor_sync(0xffffffffu, d01, 2);
    d10 += __shfl_xor_sync(0xffffffffu, d10, 1); d10 += __shfl_xor_sync(0xffffffffu, d10, 2);
    d11 += __shfl_xor_sync(0xffffffffu, d11, 1); d11 += __shfl_xor_sync(0xffffffffu, d11, 2);
    float i00 = __fdividef(1.0f, fmaxf(d00, 1e-30f));
    float i01 = __fdividef(1.0f, fmaxf(d01, 1e-30f));
    float i10 = __fdividef(1.0f, fmaxf(d10, 1e-30f));
    float i11 = __fdividef(1.0f, fmaxf(d11, 1e-30f));

    size_t col = (size_t)h * ND + 2 * cp;
    float2* out0 = (float2*)(g_attn + ((size_t)(b * NS + qw + r0) * NE + col));
    float2* out1 = (float2*)(g_attn + ((size_t)(b * NS + qw + r0 + 8) * NE + col));
    float2* out2 = (float2*)(g_attn + ((size_t)(b * NS + qw + 16 + r0) * NE + col));
    float2* out3 = (float2*)(g_attn + ((size_t)(b * NS + qw + 24 + r0) * NE + col));
    *out0 = make_float2(o0[0] * i00, o0[1] * i00);
    *out1 = make_float2(o0[2] * i01, o0[3] * i01);
    *out2 = make_float2(o1[0] * i10, o1[1] * i10);
    *out3 = make_float2(o1[2] * i11, o1[3] * i11);
}

// ---------------------------------------------------------------------------
// Kernel C: out[r, e] = sum_f attn[r, f] * w_out[e, f]
// ---------------------------------------------------------------------------
__global__ void __launch_bounds__(256) out_kernel(const float* __restrict__ w,
                                                  float* __restrict__ out) {
    extern __shared__ float sW[];   // [128][132] padded transpose
    for (int i = threadIdx.x; i < NE * NE; i += 256) {
        int e = i >> 7;
        int f = i & 127;
        sW[f * 132 + e] = w[i];
    }
    __syncthreads();

    int warp = threadIdx.x >> 5;
    int lane = threadIdx.x & 31;
    int rbase = blockIdx.x * 64 + warp * 8;

    for (int k = 0; k < 8; ++k) {
        int r = rbase + k;
        const float4* arow = (const float4*)(g_attn + (size_t)r * NE);
        float4 acc = make_float4(0.f, 0.f, 0.f, 0.f);
#pragma unroll 4
        for (int fi = 0; fi < 32; ++fi) {
            float4 a4 = arow[fi];
            int f = fi * 4;
            float4 w0 = *(const float4*)&sW[(f + 0) * 132 + lane * 4];
            acc.x = fmaf(a4.x, w0.x, acc.x);
            acc.y = fmaf(a4.x, w0.y, acc.y);
            acc.z = fmaf(a4.x, w0.z, acc.z);
            acc.w = fmaf(a4.x, w0.w, acc.w);
            float4 w1 = *(const float4*)&sW[(f + 1) * 132 + lane * 4];
            acc.x = fmaf(a4.y, w1.x, acc.x);
            acc.y = fmaf(a4.y, w1.y, acc.y);
            acc.z = fmaf(a4.y, w1.z, acc.z);
            acc.w = fmaf(a4.y, w1.w, acc.w);
            float4 w2 = *(const float4*)&sW[(f + 2) * 132 + lane * 4];
            acc.x = fmaf(a4.z, w2.x, acc.x);
            acc.y = fmaf(a4.z, w2.y, acc.y);
            acc.z = fmaf(a4.z, w2.z, acc.z);
            acc.w = fmaf(a4.z, w2.w, acc.w);
            float4 w3 = *(const float4*)&sW[(f + 3) * 132 + lane * 4];
            acc.x = fmaf(a4.w, w3.x, acc.x);
            acc.y = fmaf(a4.w, w3.y, acc.y);
            acc.z = fmaf(a4.w, w3.z, acc.z);
            acc.w = fmaf(a4.w, w3.w, acc.w);
        }
        *(float4*)(out + (size_t)r * NE + lane * 4) = acc;
    }
}

// ---------------------------------------------------------------------------
extern "C" void kernel_launch(void* const* d_in, const int* in_sizes, int n_in,
                              void* d_out, int out_size) {
    const float* x     = (const float*)d_in[0];
    const float* theta = (const float*)d_in[1];
    const float* w     = (const float*)d_in[2];
    const int*   mask  = (const int*)d_in[3];
    float*       out   = (float*)d_out;

    qgen_kernel<<<(NBH * NS) / 256, 256>>>(x, theta);

    int smB = NS * 4 * 4 * 3 + (NS / 2) * 8;   // 96 KB K/V + 8 KB bias = 106496 B
    cudaFuncSetAttribute(attn_kernel, cudaFuncAttributeMaxDynamicSharedMemorySize, smB);
    attn_kernel<<<dim3(NBH, NS / 256), 256, smB>>>(mask);

    int smC = 128 * 132 * 4;
    cudaFuncSetAttribute(out_kernel, cudaFuncAttributeMaxDynamicSharedMemorySize, smC);
    out_kernel<<<(NB * NS) / 64, 256, smC>>>(w, out);
}

// round 6
// speedup vs baseline: 2.8880x; 1.1551x over previous
#include <cuda_runtime.h>
#include <cuda_fp16.h>
#include <cstdint>

#define NB 4
#define NS 2048
#define NE 128
#define NH 16
#define ND 8
#define NBH (NB * NH)

// Staged head data (written by qgen, read by attn)
__device__ uint32_t g_kh[NBH * NS * 4];    // fp16x2 hi pairs [bh][s][4], 2 MB
__device__ uint32_t g_kl[NBH * NS * 4];    // fp16x2 lo pairs,            2 MB
__device__ uint32_t g_vp[NBH * (NS/2) * 8];// half2{v[2p][n],v[2p+1][n]},  2 MB
__device__ float    g_attn[NB * NS * NE];  // [b][s][e],                  4 MB

__device__ __forceinline__ float ex2f(float x) {
    float r; asm("ex2.approx.f32 %0,%1;" : "=f"(r) : "f"(x)); return r;
}
__device__ __forceinline__ uint32_t cvt_f16x2(float hi, float lo) {
    uint32_t r; asm("cvt.rn.f16x2.f32 %0,%1,%2;" : "=r"(r) : "f"(hi), "f"(lo)); return r;
}
__device__ __forceinline__ void mma16816(float c[4],
                                         uint32_t a0, uint32_t a1, uint32_t a2, uint32_t a3,
                                         uint32_t b0, uint32_t b1) {
    asm volatile("mma.sync.aligned.m16n8k16.row.col.f32.f16.f16.f32 "
                 "{%0,%1,%2,%3},{%4,%5,%6,%7},{%8,%9},{%0,%1,%2,%3};"
                 : "+f"(c[0]), "+f"(c[1]), "+f"(c[2]), "+f"(c[3])
                 : "r"(a0), "r"(a1), "r"(a2), "r"(a3), "r"(b0), "r"(b1));
}

// ---------------------------------------------------------------------------
// Kernel A: q = cumprod(cos(x+theta)); emit fp16 hi/lo pairs + pair-packed V.
// ---------------------------------------------------------------------------
__global__ void __launch_bounds__(128) qgen_kernel(const float* __restrict__ x,
                                                   const float* __restrict__ theta) {
    int r = blockIdx.x * blockDim.x + threadIdx.x;   // r = bh*NS + s
    if (r >= NBH * NS) return;
    int s  = r & (NS - 1);
    int bh = r >> 11;
    int h  = bh & (NH - 1);
    int b  = bh >> 4;

    const float4* xp = (const float4*)(x + ((size_t)(b * NS + s) * NE + h * ND));
    float4 x0 = xp[0], x1 = xp[1];

    float v[8];
    float p;
    p  = cosf(x0.x + theta[0]);  v[0] = p;
    p *= cosf(x0.y + theta[1]);  v[1] = p;
    p *= cosf(x0.z + theta[2]);  v[2] = p;
    p *= cosf(x0.w + theta[3]);  v[3] = p;
    p *= cosf(x1.x + theta[4]);  v[4] = p;
    p *= cosf(x1.y + theta[5]);  v[5] = p;
    p *= cosf(x1.z + theta[6]);  v[6] = p;
    p *= cosf(x1.w + theta[7]);  v[7] = p;

    uint32_t hw[4], lw[4];
#pragma unroll
    for (int j = 0; j < 4; ++j) {
        float a0 = v[2 * j], a1 = v[2 * j + 1];
        __half h0 = __float2half_rn(a0), h1 = __float2half_rn(a1);
        __half l0 = __float2half_rn(a0 - __half2float(h0));
        __half l1 = __float2half_rn(a1 - __half2float(h1));
        hw[j] = (uint32_t)__half_as_ushort(h0) | ((uint32_t)__half_as_ushort(h1) << 16);
        lw[j] = (uint32_t)__half_as_ushort(l0) | ((uint32_t)__half_as_ushort(l1) << 16);
    }
    ((uint4*)g_kh)[r] = make_uint4(hw[0], hw[1], hw[2], hw[3]);
    ((uint4*)g_kl)[r] = make_uint4(lw[0], lw[1], lw[2], lw[3]);

    // pair-packed V: g_vp[bh][s/2][n] = half2{v_even[n], v_odd[n]}
    uint16_t* vp16 = (uint16_t*)g_vp;
    size_t base = (((size_t)bh * (NS / 2) + (s >> 1)) * 8) * 2 + (s & 1);
#pragma unroll
    for (int n = 0; n < 8; ++n)
        vp16[base + 2 * n] = __half_as_ushort(__float2half_rn(v[n]));
}

// ---------------------------------------------------------------------------
// Kernel B: HMMA flash attention. CTA = (head bh, 128-query tile).
// 8 warps x 16 queries. A = [q_hi | q_lo] (exact q), B = [k_hi ; k_hi]
// => s = q * k_hi. P stays in registers, feeds PV MMA directly.
// SMEM = K_hi (32K) + V pairs (32K) + bias (8K) = 72 KB -> 3 CTAs/SM.
// ---------------------------------------------------------------------------
__global__ void __launch_bounds__(256) attn_kernel(const int* __restrict__ mask) {
    extern __shared__ char smem[];
    uint32_t* sKh = (uint32_t*)smem;                    // 2048*4 u32 = 32 KB
    uint32_t* sVp = sKh + NS * 4;                       // 32 KB
    float2*   sB  = (float2*)(sVp + NS * 4);            //  8 KB

    int tid = threadIdx.x;
    int bh = blockIdx.x;
    int b  = bh >> 4;
    int h  = bh & (NH - 1);

    {   // stage K_hi + V pairs + mask bias
        const uint4* gh = (const uint4*)(g_kh + (size_t)bh * NS * 4);
        const uint4* gv = (const uint4*)(g_vp + (size_t)bh * (NS / 2) * 8);
        uint4* sh4 = (uint4*)sKh;
        uint4* sv4 = (uint4*)sVp;
        for (int i = tid; i < NS; i += 256) { sh4[i] = gh[i]; sv4[i] = gv[i]; }
        const int* mrow = mask + b * NS;
        for (int i = tid; i < NS / 2; i += 256)
            sB[i] = make_float2(mrow[2 * i] ? 0.0f : -1.0e9f,
                                mrow[2 * i + 1] ? 0.0f : -1.0e9f);
    }
    __syncthreads();

    int warp = tid >> 5, lane = tid & 31;
    int r0 = lane >> 2, cp = lane & 3;
    int qw = blockIdx.y * 128 + warp * 16;              // warp's first query

    // A fragment (16 queries x 16 K-cols = [q_hi(8) | q_lo(8)]), from GMEM once
    const uint32_t* gkh = g_kh + (size_t)bh * NS * 4;
    const uint32_t* gkl = g_kl + (size_t)bh * NS * 4;
    uint32_t A0 = gkh[(qw + r0) * 4 + cp];
    uint32_t A1 = gkh[(qw + r0 + 8) * 4 + cp];
    uint32_t A2 = gkl[(qw + r0) * 4 + cp];
    uint32_t A3 = gkl[(qw + r0 + 8) * 4 + cp];

    const float CL = 0.51010205144336435f;  // log2(e) / sqrt(8)

    float o[4] = {0.f, 0.f, 0.f, 0.f};
    float d0 = 0.f, d1 = 0.f;               // rows r0, r0+8

#pragma unroll 2
    for (int kb = 0; kb < NS; kb += 16) {
        uint32_t bh0 = sKh[(kb + r0) * 4 + cp];       // keys kb..kb+7
        uint32_t bh1 = sKh[(kb + 8 + r0) * 4 + cp];   // keys kb+8..kb+15
        float c0[4] = {0.f, 0.f, 0.f, 0.f};
        float c1[4] = {0.f, 0.f, 0.f, 0.f};
        mma16816(c0, A0, A1, A2, A3, bh0, bh0);
        mma16816(c1, A0, A1, A2, A3, bh1, bh1);

        float2 bi0 = sB[(kb >> 1) + cp];
        float2 bi1 = sB[(kb >> 1) + 4 + cp];
        float e0 = ex2f(fmaf(c0[0], CL, bi0.x));
        float e1 = ex2f(fmaf(c0[1], CL, bi0.y));
        float e2 = ex2f(fmaf(c0[2], CL, bi0.x));
        float e3 = ex2f(fmaf(c0[3], CL, bi0.y));
        float f0 = ex2f(fmaf(c1[0], CL, bi1.x));
        float f1 = ex2f(fmaf(c1[1], CL, bi1.y));
        float f2 = ex2f(fmaf(c1[2], CL, bi1.x));
        float f3 = ex2f(fmaf(c1[3], CL, bi1.y));
        d0 += e0 + e1 + f0 + f1;
        d1 += e2 + e3 + f2 + f3;

        uint32_t pe0 = cvt_f16x2(e1, e0);   // P frag: k cols 0-7   (c0)
        uint32_t pe1 = cvt_f16x2(e3, e2);
        uint32_t po0 = cvt_f16x2(f1, f0);   //          k cols 8-15 (c1)
        uint32_t po1 = cvt_f16x2(f3, f2);

        uint32_t vb0 = sVp[((kb >> 1) + cp) * 8 + r0];
        uint32_t vb1 = sVp[((kb >> 1) + 4 + cp) * 8 + r0];
        mma16816(o, pe0, pe1, po0, po1, vb0, vb1);
    }

    // reduce den across the quad (lanes holding different key columns)
    d0 += __shfl_xor_sync(0xffffffffu, d0, 1); d0 += __shfl_xor_sync(0xffffffffu, d0, 2);
    d1 += __shfl_xor_sync(0xffffffffu, d1, 1); d1 += __shfl_xor_sync(0xffffffffu, d1, 2);
    float i0 = __fdividef(1.0f, fmaxf(d0, 1e-30f));
    float i1 = __fdividef(1.0f, fmaxf(d1, 1e-30f));

    size_t col = (size_t)h * ND + 2 * cp;
    float2* out0 = (float2*)(g_attn + ((size_t)(b * NS + qw + r0) * NE + col));
    float2* out1 = (float2*)(g_attn + ((size_t)(b * NS + qw + r0 + 8) * NE + col));
    *out0 = make_float2(o[0] * i0, o[1] * i0);
    *out1 = make_float2(o[2] * i1, o[3] * i1);
}

// ---------------------------------------------------------------------------
// Kernel C: out[r, e] = sum_f attn[r, f] * w_out[e, f]
// ---------------------------------------------------------------------------
__global__ void __launch_bounds__(256) out_kernel(const float* __restrict__ w,
                                                  float* __restrict__ out) {
    extern __shared__ float sW[];   // [128][132] padded transpose
    for (int i = threadIdx.x; i < NE * NE; i += 256) {
        int e = i >> 7;
        int f = i & 127;
        sW[f * 132 + e] = w[i];
    }
    __syncthreads();

    int warp = threadIdx.x >> 5;
    int lane = threadIdx.x & 31;
    int rbase = blockIdx.x * 64 + warp * 8;

    for (int k = 0; k < 8; ++k) {
        int r = rbase + k;
        const float4* arow = (const float4*)(g_attn + (size_t)r * NE);
        float4 acc = make_float4(0.f, 0.f, 0.f, 0.f);
#pragma unroll 4
        for (int fi = 0; fi < 32; ++fi) {
            float4 a4 = arow[fi];
            int f = fi * 4;
            float4 w0 = *(const float4*)&sW[(f + 0) * 132 + lane * 4];
            acc.x = fmaf(a4.x, w0.x, acc.x);
            acc.y = fmaf(a4.x, w0.y, acc.y);
            acc.z = fmaf(a4.x, w0.z, acc.z);
            acc.w = fmaf(a4.x, w0.w, acc.w);
            float4 w1 = *(const float4*)&sW[(f + 1) * 132 + lane * 4];
            acc.x = fmaf(a4.y, w1.x, acc.x);
            acc.y = fmaf(a4.y, w1.y, acc.y);
            acc.z = fmaf(a4.y, w1.z, acc.z);
            acc.w = fmaf(a4.y, w1.w, acc.w);
            float4 w2 = *(const float4*)&sW[(f + 2) * 132 + lane * 4];
            acc.x = fmaf(a4.z, w2.x, acc.x);
            acc.y = fmaf(a4.z, w2.y, acc.y);
            acc.z = fmaf(a4.z, w2.z, acc.z);
            acc.w = fmaf(a4.z, w2.w, acc.w);
            float4 w3 = *(const float4*)&sW[(f + 3) * 132 + lane * 4];
            acc.x = fmaf(a4.w, w3.x, acc.x);
            acc.y = fmaf(a4.w, w3.y, acc.y);
            acc.z = fmaf(a4.w, w3.z, acc.z);
            acc.w = fmaf(a4.w, w3.w, acc.w);
        }
        *(float4*)(out + (size_t)r * NE + lane * 4) = acc;
    }
}

// ---------------------------------------------------------------------------
extern "C" void kernel_launch(void* const* d_in, const int* in_sizes, int n_in,
                              void* d_out, int out_size) {
    const float* x     = (const float*)d_in[0];
    const float* theta = (const float*)d_in[1];
    const float* w     = (const float*)d_in[2];
    const int*   mask  = (const int*)d_in[3];
    float*       out   = (float*)d_out;

    qgen_kernel<<<(NBH * NS) / 128, 128>>>(x, theta);

    int smB = NS * 4 * 4 * 2 + (NS / 2) * 8;   // 64 KB K/V + 8 KB bias = 73728 B
    cudaFuncSetAttribute(attn_kernel, cudaFuncAttributeMaxDynamicSharedMemorySize, smB);
    attn_kernel<<<dim3(NBH, NS / 128), 256, smB>>>(mask);

    int smC = 128 * 132 * 4;
    cudaFuncSetAttribute(out_kernel, cudaFuncAttributeMaxDynamicSharedMemorySize, smC);
    out_kernel<<<(NB * NS) / 64, 256, smC>>>(w, out);
}

// round 7
// speedup vs baseline: 3.7627x; 1.3029x over previous
#include <cuda_runtime.h>
#include <cuda_fp16.h>
#include <cstdint>

#define NB 4
#define NS 2048
#define NE 128
#define NH 16
#define ND 8
#define NBH (NB * NH)

// Staged head data (written by qgen, read by attn)
// g_kh/g_kl hold hi/lo fp16 of (sqrt(log2e/sqrt(8)) * q)  -> score MMA operands
// g_vp holds pair-packed fp16 of (raw v * mask)           -> PV MMA B operand
__device__ uint32_t g_kh[NBH * NS * 4];     // 2 MB
__device__ uint32_t g_kl[NBH * NS * 4];     // 2 MB
__device__ uint32_t g_vp[NBH * (NS/2) * 8]; // 2 MB
__device__ float    g_attn[NB * NS * NE];   // 4 MB

__device__ __forceinline__ uint32_t cvt_f16x2(float hi, float lo) {
    uint32_t r; asm("cvt.rn.f16x2.f32 %0,%1,%2;" : "=r"(r) : "f"(hi), "f"(lo)); return r;
}
__device__ __forceinline__ uint32_t ex2h2(uint32_t x) {
    uint32_t r; asm("ex2.approx.f16x2 %0,%1;" : "=r"(r) : "r"(x)); return r;
}
__device__ __forceinline__ void mma16816(float c[4],
                                         uint32_t a0, uint32_t a1, uint32_t a2, uint32_t a3,
                                         uint32_t b0, uint32_t b1) {
    asm volatile("mma.sync.aligned.m16n8k16.row.col.f32.f16.f16.f32 "
                 "{%0,%1,%2,%3},{%4,%5,%6,%7},{%8,%9},{%0,%1,%2,%3};"
                 : "+f"(c[0]), "+f"(c[1]), "+f"(c[2]), "+f"(c[3])
                 : "r"(a0), "r"(a1), "r"(a2), "r"(a3), "r"(b0), "r"(b1));
}

// ---------------------------------------------------------------------------
// Kernel A: q = cumprod(cos(x+theta)); emit sqrtCL-scaled hi/lo fp16 pairs
// (score operands) + mask-folded pair-packed V.
// ---------------------------------------------------------------------------
__global__ void __launch_bounds__(128) qgen_kernel(const float* __restrict__ x,
                                                   const float* __restrict__ theta,
                                                   const int* __restrict__ mask) {
    int r = blockIdx.x * blockDim.x + threadIdx.x;   // r = bh*NS + s
    if (r >= NBH * NS) return;
    int s  = r & (NS - 1);
    int bh = r >> 11;
    int h  = bh & (NH - 1);
    int b  = bh >> 4;

    const float4* xp = (const float4*)(x + ((size_t)(b * NS + s) * NE + h * ND));
    float4 x0 = xp[0], x1 = xp[1];

    float v[8];
    float p;
    p  = cosf(x0.x + theta[0]);  v[0] = p;
    p *= cosf(x0.y + theta[1]);  v[1] = p;
    p *= cosf(x0.z + theta[2]);  v[2] = p;
    p *= cosf(x0.w + theta[3]);  v[3] = p;
    p *= cosf(x1.x + theta[4]);  v[4] = p;
    p *= cosf(x1.y + theta[5]);  v[5] = p;
    p *= cosf(x1.z + theta[6]);  v[6] = p;
    p *= cosf(x1.w + theta[7]);  v[7] = p;

    // sqrt(log2(e)/sqrt(8)) folded into BOTH score operands
    const float CLS = 0.71421430302f;   // sqrt(0.51010205144336435)
    uint32_t hw[4], lw[4];
#pragma unroll
    for (int j = 0; j < 4; ++j) {
        float a0 = v[2 * j] * CLS, a1 = v[2 * j + 1] * CLS;
        __half h0 = __float2half_rn(a0), h1 = __float2half_rn(a1);
        __half l0 = __float2half_rn(a0 - __half2float(h0));
        __half l1 = __float2half_rn(a1 - __half2float(h1));
        hw[j] = (uint32_t)__half_as_ushort(h0) | ((uint32_t)__half_as_ushort(h1) << 16);
        lw[j] = (uint32_t)__half_as_ushort(l0) | ((uint32_t)__half_as_ushort(l1) << 16);
    }
    ((uint4*)g_kh)[r] = make_uint4(hw[0], hw[1], hw[2], hw[3]);
    ((uint4*)g_kl)[r] = make_uint4(lw[0], lw[1], lw[2], lw[3]);

    // pair-packed V with mask folded: g_vp[bh][s/2][n] = half2{v*m (even), (odd)}
    float m = (float)mask[b * NS + s];
    uint16_t* vp16 = (uint16_t*)g_vp;
    size_t base = (((size_t)bh * (NS / 2) + (s >> 1)) * 8) * 2 + (s & 1);
#pragma unroll
    for (int n = 0; n < 8; ++n)
        vp16[base + 2 * n] = __half_as_ushort(__float2half_rn(v[n] * m));
}

// ---------------------------------------------------------------------------
// Kernel B: HMMA flash attention. CTA = (head bh, 128-query tile), 8 warps.
// Per 16q x 16k iter: 2 score HMMA -> cvt f16x2 -> ex2.f16x2 -> P frags
//   -> PV HMMA (V, mask-folded) + den HMMA (B = fp16 mask pairs).
// No FFMA/FADD/shuffle epilogue at all.
// ---------------------------------------------------------------------------
__global__ void __launch_bounds__(256) attn_kernel(const int* __restrict__ mask) {
    extern __shared__ char smem[];
    uint32_t* sKh = (uint32_t*)smem;                    // 32 KB
    uint32_t* sVp = sKh + NS * 4;                       // 32 KB
    uint32_t* sVm = sVp + NS * 4;                       //  4 KB fp16x2 mask pairs

    int tid = threadIdx.x;
    int bh = blockIdx.x;
    int b  = bh >> 4;
    int h  = bh & (NH - 1);

    {   // stage K_hi + V pairs + mask pairs
        const uint4* gh = (const uint4*)(g_kh + (size_t)bh * NS * 4);
        const uint4* gv = (const uint4*)(g_vp + (size_t)bh * (NS / 2) * 8);
        uint4* sh4 = (uint4*)sKh;
        uint4* sv4 = (uint4*)sVp;
        for (int i = tid; i < NS; i += 256) { sh4[i] = gh[i]; sv4[i] = gv[i]; }
        const int* mrow = mask + b * NS;
        for (int i = tid; i < NS / 2; i += 256) {
            __half m0 = __float2half_rn((float)mrow[2 * i]);
            __half m1 = __float2half_rn((float)mrow[2 * i + 1]);
            sVm[i] = (uint32_t)__half_as_ushort(m0) | ((uint32_t)__half_as_ushort(m1) << 16);
        }
    }
    __syncthreads();

    int warp = tid >> 5, lane = tid & 31;
    int r0 = lane >> 2, cp = lane & 3;
    int qw = blockIdx.y * 128 + warp * 16;              // warp's first query

    // A fragment (16 queries x 16 K-cols = [qs_hi(8) | qs_lo(8)]), from GMEM once
    const uint32_t* gkh = g_kh + (size_t)bh * NS * 4;
    const uint32_t* gkl = g_kl + (size_t)bh * NS * 4;
    uint32_t A0 = gkh[(qw + r0) * 4 + cp];
    uint32_t A1 = gkh[(qw + r0 + 8) * 4 + cp];
    uint32_t A2 = gkl[(qw + r0) * 4 + cp];
    uint32_t A3 = gkl[(qw + r0 + 8) * 4 + cp];

    float o[4]  = {0.f, 0.f, 0.f, 0.f};     // PV accumulator
    float o2[4] = {0.f, 0.f, 0.f, 0.f};     // den accumulator

#pragma unroll 2
    for (int kb = 0; kb < NS; kb += 16) {
        uint32_t bh0 = sKh[(kb + r0) * 4 + cp];       // keys kb..kb+7
        uint32_t bh1 = sKh[(kb + 8 + r0) * 4 + cp];   // keys kb+8..kb+15
        float c0[4] = {0.f, 0.f, 0.f, 0.f};
        float c1[4] = {0.f, 0.f, 0.f, 0.f};
        mma16816(c0, A0, A1, A2, A3, bh0, bh0);
        mma16816(c1, A0, A1, A2, A3, bh1, bh1);

        // e = 2^c computed two-wide in fp16; results ARE the P fragments
        uint32_t pe0 = ex2h2(cvt_f16x2(c0[1], c0[0]));
        uint32_t pe1 = ex2h2(cvt_f16x2(c0[3], c0[2]));
        uint32_t po0 = ex2h2(cvt_f16x2(c1[1], c1[0]));
        uint32_t po1 = ex2h2(cvt_f16x2(c1[3], c1[2]));

        uint32_t vb0 = sVp[((kb >> 1) + cp) * 8 + r0];
        uint32_t vb1 = sVp[((kb >> 1) + 4 + cp) * 8 + r0];
        uint32_t vm0 = sVm[(kb >> 1) + cp];
        uint32_t vm1 = sVm[(kb >> 1) + 4 + cp];
        mma16816(o,  pe0, pe1, po0, po1, vb0, vb1);   // numerator
        mma16816(o2, pe0, pe1, po0, po1, vm0, vm1);   // denominator (masked)
    }

    // den already reduced over keys by the MMA: row r0 -> o2[0], row r0+8 -> o2[2]
    float i0 = __fdividef(1.0f, fmaxf(o2[0], 1e-30f));
    float i1 = __fdividef(1.0f, fmaxf(o2[2], 1e-30f));

    size_t col = (size_t)h * ND + 2 * cp;
    float2* out0 = (float2*)(g_attn + ((size_t)(b * NS + qw + r0) * NE + col));
    float2* out1 = (float2*)(g_attn + ((size_t)(b * NS + qw + r0 + 8) * NE + col));
    *out0 = make_float2(o[0] * i0, o[1] * i0);
    *out1 = make_float2(o[2] * i1, o[3] * i1);
}

// ---------------------------------------------------------------------------
// Kernel C: out[r, e] = sum_f attn[r, f] * w_out[e, f]
// ---------------------------------------------------------------------------
__global__ void __launch_bounds__(256) out_kernel(const float* __restrict__ w,
                                                  float* __restrict__ out) {
    extern __shared__ float sW[];   // [128][132] padded transpose
    for (int i = threadIdx.x; i < NE * NE; i += 256) {
        int e = i >> 7;
        int f = i & 127;
        sW[f * 132 + e] = w[i];
    }
    __syncthreads();

    int warp = threadIdx.x >> 5;
    int lane = threadIdx.x & 31;
    int rbase = blockIdx.x * 64 + warp * 8;

    for (int k = 0; k < 8; ++k) {
        int r = rbase + k;
        const float4* arow = (const float4*)(g_attn + (size_t)r * NE);
        float4 acc = make_float4(0.f, 0.f, 0.f, 0.f);
#pragma unroll 4
        for (int fi = 0; fi < 32; ++fi) {
            float4 a4 = arow[fi];
            int f = fi * 4;
            float4 w0 = *(const float4*)&sW[(f + 0) * 132 + lane * 4];
            acc.x = fmaf(a4.x, w0.x, acc.x);
            acc.y = fmaf(a4.x, w0.y, acc.y);
            acc.z = fmaf(a4.x, w0.z, acc.z);
            acc.w = fmaf(a4.x, w0.w, acc.w);
            float4 w1 = *(const float4*)&sW[(f + 1) * 132 + lane * 4];
            acc.x = fmaf(a4.y, w1.x, acc.x);
            acc.y = fmaf(a4.y, w1.y, acc.y);
            acc.z = fmaf(a4.y, w1.z, acc.z);
            acc.w = fmaf(a4.y, w1.w, acc.w);
            float4 w2 = *(const float4*)&sW[(f + 2) * 132 + lane * 4];
            acc.x = fmaf(a4.z, w2.x, acc.x);
            acc.y = fmaf(a4.z, w2.y, acc.y);
            acc.z = fmaf(a4.z, w2.z, acc.z);
            acc.w = fmaf(a4.z, w2.w, acc.w);
            float4 w3 = *(const float4*)&sW[(f + 3) * 132 + lane * 4];
            acc.x = fmaf(a4.w, w3.x, acc.x);
            acc.y = fmaf(a4.w, w3.y, acc.y);
            acc.z = fmaf(a4.w, w3.z, acc.z);
            acc.w = fmaf(a4.w, w3.w, acc.w);
        }
        *(float4*)(out + (size_t)r * NE + lane * 4) = acc;
    }
}

// ---------------------------------------------------------------------------
extern "C" void kernel_launch(void* const* d_in, const int* in_sizes, int n_in,
                              void* d_out, int out_size) {
    const float* x     = (const float*)d_in[0];
    const float* theta = (const float*)d_in[1];
    const float* w     = (const float*)d_in[2];
    const int*   mask  = (const int*)d_in[3];
    float*       out   = (float*)d_out;

    qgen_kernel<<<(NBH * NS) / 128, 128>>>(x, theta, mask);

    int smB = NS * 4 * 4 * 2 + (NS / 2) * 4;   // 64 KB K/V + 4 KB mask = 69632 B
    cudaFuncSetAttribute(attn_kernel, cudaFuncAttributeMaxDynamicSharedMemorySize, smB);
    attn_kernel<<<dim3(NBH, NS / 128), 256, smB>>>(mask);

    int smC = 128 * 132 * 4;
    cudaFuncSetAttribute(out_kernel, cudaFuncAttributeMaxDynamicSharedMemorySize, smC);
    out_kernel<<<(NB * NS) / 64, 256, smC>>>(w, out);
}

// round 8
// speedup vs baseline: 3.9055x; 1.0379x over previous
#include <cuda_runtime.h>
#include <cuda_fp16.h>
#include <cstdint>

#define NB 4
#define NS 2048
#define NE 128
#define NH 16
#define ND 8
#define NBH (NB * NH)

// Staged head data (written by qgen, read by attn)
// g_kh holds fp16 pairs of (sqrt(log2e/sqrt(8)) * q)  -> score MMA operands (A and B)
// g_vp holds pair-packed fp16 of (raw v * mask)       -> PV MMA B operand
__device__ uint32_t g_kh[NBH * NS * 4];     // 2 MB
__device__ uint32_t g_vp[NBH * (NS/2) * 8]; // 2 MB
__device__ float    g_attn[NB * NS * NE];   // 4 MB

__device__ __forceinline__ uint32_t cvt_f16x2(float hi, float lo) {
    uint32_t r; asm("cvt.rn.f16x2.f32 %0,%1,%2;" : "=r"(r) : "f"(hi), "f"(lo)); return r;
}
__device__ __forceinline__ uint32_t ex2h2(uint32_t x) {
    uint32_t r; asm("ex2.approx.f16x2 %0,%1;" : "=r"(r) : "r"(x)); return r;
}
// score MMA: m16n8k8 (K = 8 head dims), half the MACs of k16
__device__ __forceinline__ void mma16808(float c[4], uint32_t a0, uint32_t a1, uint32_t b0) {
    asm volatile("mma.sync.aligned.m16n8k8.row.col.f32.f16.f16.f32 "
                 "{%0,%1,%2,%3},{%4,%5},{%6},{%0,%1,%2,%3};"
                 : "+f"(c[0]), "+f"(c[1]), "+f"(c[2]), "+f"(c[3])
                 : "r"(a0), "r"(a1), "r"(b0));
}
__device__ __forceinline__ void mma16816(float c[4],
                                         uint32_t a0, uint32_t a1, uint32_t a2, uint32_t a3,
                                         uint32_t b0, uint32_t b1) {
    asm volatile("mma.sync.aligned.m16n8k16.row.col.f32.f16.f16.f32 "
                 "{%0,%1,%2,%3},{%4,%5,%6,%7},{%8,%9},{%0,%1,%2,%3};"
                 : "+f"(c[0]), "+f"(c[1]), "+f"(c[2]), "+f"(c[3])
                 : "r"(a0), "r"(a1), "r"(a2), "r"(a3), "r"(b0), "r"(b1));
}

// ---------------------------------------------------------------------------
// Kernel A: q = cumprod(cos(x+theta)); emit sqrtCL-scaled fp16 pairs
// (score operands) + mask-folded pair-packed V.
// ---------------------------------------------------------------------------
__global__ void __launch_bounds__(128) qgen_kernel(const float* __restrict__ x,
                                                   const float* __restrict__ theta,
                                                   const int* __restrict__ mask) {
    int r = blockIdx.x * blockDim.x + threadIdx.x;   // r = bh*NS + s
    if (r >= NBH * NS) return;
    int s  = r & (NS - 1);
    int bh = r >> 11;
    int h  = bh & (NH - 1);
    int b  = bh >> 4;

    const float4* xp = (const float4*)(x + ((size_t)(b * NS + s) * NE + h * ND));
    float4 x0 = xp[0], x1 = xp[1];

    float v[8];
    float p;
    p  = cosf(x0.x + theta[0]);  v[0] = p;
    p *= cosf(x0.y + theta[1]);  v[1] = p;
    p *= cosf(x0.z + theta[2]);  v[2] = p;
    p *= cosf(x0.w + theta[3]);  v[3] = p;
    p *= cosf(x1.x + theta[4]);  v[4] = p;
    p *= cosf(x1.y + theta[5]);  v[5] = p;
    p *= cosf(x1.z + theta[6]);  v[6] = p;
    p *= cosf(x1.w + theta[7]);  v[7] = p;

    // sqrt(log2(e)/sqrt(8)) folded into BOTH score operands
    const float CLS = 0.71421430302f;   // sqrt(0.51010205144336435)
    uint32_t hw[4];
#pragma unroll
    for (int j = 0; j < 4; ++j) {
        __half h0 = __float2half_rn(v[2 * j] * CLS);
        __half h1 = __float2half_rn(v[2 * j + 1] * CLS);
        hw[j] = (uint32_t)__half_as_ushort(h0) | ((uint32_t)__half_as_ushort(h1) << 16);
    }
    ((uint4*)g_kh)[r] = make_uint4(hw[0], hw[1], hw[2], hw[3]);

    // pair-packed V with mask folded: g_vp[bh][s/2][n] = half2{v*m (even), (odd)}
    float m = (float)mask[b * NS + s];
    uint16_t* vp16 = (uint16_t*)g_vp;
    size_t base = (((size_t)bh * (NS / 2) + (s >> 1)) * 8) * 2 + (s & 1);
#pragma unroll
    for (int n = 0; n < 8; ++n)
        vp16[base + 2 * n] = __half_as_ushort(__float2half_rn(v[n] * m));
}

// ---------------------------------------------------------------------------
// Kernel B: HMMA flash attention. CTA = (head bh, 128-query tile), 8 warps.
// Per 16q x 16k iter: 2 score HMMA (m16n8k8) -> cvt f16x2 -> ex2.f16x2
//   -> PV HMMA (V, mask-folded) + den HMMA (B = fp16 mask pairs), both k16.
// ---------------------------------------------------------------------------
__global__ void __launch_bounds__(256) attn_kernel(const int* __restrict__ mask) {
    extern __shared__ char smem[];
    uint32_t* sKh = (uint32_t*)smem;                    // 32 KB
    uint32_t* sVp = sKh + NS * 4;                       // 32 KB
    uint32_t* sVm = sVp + NS * 4;                       //  4 KB fp16x2 mask pairs

    int tid = threadIdx.x;
    int bh = blockIdx.x;
    int b  = bh >> 4;
    int h  = bh & (NH - 1);

    {   // stage K + V pairs + mask pairs
        const uint4* gh = (const uint4*)(g_kh + (size_t)bh * NS * 4);
        const uint4* gv = (const uint4*)(g_vp + (size_t)bh * (NS / 2) * 8);
        uint4* sh4 = (uint4*)sKh;
        uint4* sv4 = (uint4*)sVp;
        for (int i = tid; i < NS; i += 256) { sh4[i] = gh[i]; sv4[i] = gv[i]; }
        const int* mrow = mask + b * NS;
        for (int i = tid; i < NS / 2; i += 256) {
            __half m0 = __float2half_rn((float)mrow[2 * i]);
            __half m1 = __float2half_rn((float)mrow[2 * i + 1]);
            sVm[i] = (uint32_t)__half_as_ushort(m0) | ((uint32_t)__half_as_ushort(m1) << 16);
        }
    }
    __syncthreads();

    int warp = tid >> 5, lane = tid & 31;
    int r0 = lane >> 2, cp = lane & 3;
    int qw = blockIdx.y * 128 + warp * 16;              // warp's first query

    // A fragment (16 queries x 8 dims), 2 regs, from GMEM once
    const uint32_t* gkh = g_kh + (size_t)bh * NS * 4;
    uint32_t A0 = gkh[(qw + r0) * 4 + cp];
    uint32_t A1 = gkh[(qw + r0 + 8) * 4 + cp];

    float o[4]  = {0.f, 0.f, 0.f, 0.f};     // PV accumulator
    float o2[4] = {0.f, 0.f, 0.f, 0.f};     // den accumulator

#pragma unroll 2
    for (int kb = 0; kb < NS; kb += 16) {
        uint32_t bh0 = sKh[(kb + r0) * 4 + cp];       // keys kb..kb+7
        uint32_t bh1 = sKh[(kb + 8 + r0) * 4 + cp];   // keys kb+8..kb+15
        float c0[4] = {0.f, 0.f, 0.f, 0.f};
        float c1[4] = {0.f, 0.f, 0.f, 0.f};
        mma16808(c0, A0, A1, bh0);
        mma16808(c1, A0, A1, bh1);

        // e = 2^c computed two-wide in fp16; results ARE the P fragments
        uint32_t pe0 = ex2h2(cvt_f16x2(c0[1], c0[0]));
        uint32_t pe1 = ex2h2(cvt_f16x2(c0[3], c0[2]));
        uint32_t po0 = ex2h2(cvt_f16x2(c1[1], c1[0]));
        uint32_t po1 = ex2h2(cvt_f16x2(c1[3], c1[2]));

        uint32_t vb0 = sVp[((kb >> 1) + cp) * 8 + r0];
        uint32_t vb1 = sVp[((kb >> 1) + 4 + cp) * 8 + r0];
        uint32_t vm0 = sVm[(kb >> 1) + cp];
        uint32_t vm1 = sVm[(kb >> 1) + 4 + cp];
        mma16816(o,  pe0, pe1, po0, po1, vb0, vb1);   // numerator
        mma16816(o2, pe0, pe1, po0, po1, vm0, vm1);   // denominator (masked)
    }

    // den already reduced over keys by the MMA: row r0 -> o2[0], row r0+8 -> o2[2]
    float i0 = __fdividef(1.0f, fmaxf(o2[0], 1e-30f));
    float i1 = __fdividef(1.0f, fmaxf(o2[2], 1e-30f));

    size_t col = (size_t)h * ND + 2 * cp;
    float2* out0 = (float2*)(g_attn + ((size_t)(b * NS + qw + r0) * NE + col));
    float2* out1 = (float2*)(g_attn + ((size_t)(b * NS + qw + r0 + 8) * NE + col));
    *out0 = make_float2(o[0] * i0, o[1] * i0);
    *out1 = make_float2(o[2] * i1, o[3] * i1);
}

// ---------------------------------------------------------------------------
// Kernel C: out[r, e] = sum_f attn[r, f] * w_out[e, f]
// ---------------------------------------------------------------------------
__global__ void __launch_bounds__(256) out_kernel(const float* __restrict__ w,
                                                  float* __restrict__ out) {
    extern __shared__ float sW[];   // [128][132] padded transpose
    for (int i = threadIdx.x; i < NE * NE; i += 256) {
        int e = i >> 7;
        int f = i & 127;
        sW[f * 132 + e] = w[i];
    }
    __syncthreads();

    int warp = threadIdx.x >> 5;
    int lane = threadIdx.x & 31;
    int rbase = blockIdx.x * 64 + warp * 8;

    for (int k = 0; k < 8; ++k) {
        int r = rbase + k;
        const float4* arow = (const float4*)(g_attn + (size_t)r * NE);
        float4 acc = make_float4(0.f, 0.f, 0.f, 0.f);
#pragma unroll 4
        for (int fi = 0; fi < 32; ++fi) {
            float4 a4 = arow[fi];
            int f = fi * 4;
            float4 w0 = *(const float4*)&sW[(f + 0) * 132 + lane * 4];
            acc.x = fmaf(a4.x, w0.x, acc.x);
            acc.y = fmaf(a4.x, w0.y, acc.y);
            acc.z = fmaf(a4.x, w0.z, acc.z);
            acc.w = fmaf(a4.x, w0.w, acc.w);
            float4 w1 = *(const float4*)&sW[(f + 1) * 132 + lane * 4];
            acc.x = fmaf(a4.y, w1.x, acc.x);
            acc.y = fmaf(a4.y, w1.y, acc.y);
            acc.z = fmaf(a4.y, w1.z, acc.z);
            acc.w = fmaf(a4.y, w1.w, acc.w);
            float4 w2 = *(const float4*)&sW[(f + 2) * 132 + lane * 4];
            acc.x = fmaf(a4.z, w2.x, acc.x);
            acc.y = fmaf(a4.z, w2.y, acc.y);
            acc.z = fmaf(a4.z, w2.z, acc.z);
            acc.w = fmaf(a4.z, w2.w, acc.w);
            float4 w3 = *(const float4*)&sW[(f + 3) * 132 + lane * 4];
            acc.x = fmaf(a4.w, w3.x, acc.x);
            acc.y = fmaf(a4.w, w3.y, acc.y);
            acc.z = fmaf(a4.w, w3.z, acc.z);
            acc.w = fmaf(a4.w, w3.w, acc.w);
        }
        *(float4*)(out + (size_t)r * NE + lane * 4) = acc;
    }
}

// ---------------------------------------------------------------------------
extern "C" void kernel_launch(void* const* d_in, const int* in_sizes, int n_in,
                              void* d_out, int out_size) {
    const float* x     = (const float*)d_in[0];
    const float* theta = (const float*)d_in[1];
    const float* w     = (const float*)d_in[2];
    const int*   mask  = (const int*)d_in[3];
    float*       out   = (float*)d_out;

    qgen_kernel<<<(NBH * NS) / 128, 128>>>(x, theta, mask);

    int smB = NS * 4 * 4 * 2 + (NS / 2) * 4;   // 64 KB K/V + 4 KB mask = 69632 B
    cudaFuncSetAttribute(attn_kernel, cudaFuncAttributeMaxDynamicSharedMemorySize, smB);
    attn_kernel<<<dim3(NBH, NS / 128), 256, smB>>>(mask);

    int smC = 128 * 132 * 4;
    cudaFuncSetAttribute(out_kernel, cudaFuncAttributeMaxDynamicSharedMemorySize, smC);
    out_kernel<<<(NB * NS) / 64, 256, smC>>>(w, out);
}

// round 9
// speedup vs baseline: 3.9714x; 1.0169x over previous
#include <cuda_runtime.h>
#include <cuda_fp16.h>
#include <cstdint>

#define NB 4
#define NS 2048
#define NE 128
#define NH 16
#define ND 8
#define NBH (NB * NH)

// Staged head data (written by qgen, read by attn)
// g_kh holds fp16 pairs of (sqrt(log2e/sqrt(8)) * q)  -> score MMA operands (A and B)
// g_vp holds pair-packed fp16 of (raw v * mask)       -> PV MMA B operand
__device__ uint32_t g_kh[NBH * NS * 4];     // 2 MB
__device__ uint32_t g_vp[NBH * (NS/2) * 8]; // 2 MB
__device__ float    g_attn[NB * NS * NE];   // 4 MB

__device__ __forceinline__ uint32_t ex2h2(uint32_t x) {
    uint32_t r; asm("ex2.approx.f16x2 %0,%1;" : "=r"(r) : "r"(x)); return r;
}
// score MMA: m16n8k8, fp16 accumulate -> D already packed f16x2
__device__ __forceinline__ void mma16808h(uint32_t& dlo, uint32_t& dhi,
                                          uint32_t a0, uint32_t a1, uint32_t b0) {
    asm volatile("mma.sync.aligned.m16n8k8.row.col.f16.f16.f16.f16 "
                 "{%0,%1},{%2,%3},{%4},{%5,%5};"
                 : "=r"(dlo), "=r"(dhi)
                 : "r"(a0), "r"(a1), "r"(b0), "r"(0u));
}
__device__ __forceinline__ void mma16816(float c[4],
                                         uint32_t a0, uint32_t a1, uint32_t a2, uint32_t a3,
                                         uint32_t b0, uint32_t b1) {
    asm volatile("mma.sync.aligned.m16n8k16.row.col.f32.f16.f16.f32 "
                 "{%0,%1,%2,%3},{%4,%5,%6,%7},{%8,%9},{%0,%1,%2,%3};"
                 : "+f"(c[0]), "+f"(c[1]), "+f"(c[2]), "+f"(c[3])
                 : "r"(a0), "r"(a1), "r"(a2), "r"(a3), "r"(b0), "r"(b1));
}

// ---------------------------------------------------------------------------
// Kernel A: q = cumprod(cos(x+theta)); emit sqrtCL-scaled fp16 pairs
// (score operands) + mask-folded pair-packed V.
// ---------------------------------------------------------------------------
__global__ void __launch_bounds__(128) qgen_kernel(const float* __restrict__ x,
                                                   const float* __restrict__ theta,
                                                   const int* __restrict__ mask) {
    int r = blockIdx.x * blockDim.x + threadIdx.x;   // r = bh*NS + s
    if (r >= NBH * NS) return;
    int s  = r & (NS - 1);
    int bh = r >> 11;
    int h  = bh & (NH - 1);
    int b  = bh >> 4;

    const float4* xp = (const float4*)(x + ((size_t)(b * NS + s) * NE + h * ND));
    float4 x0 = xp[0], x1 = xp[1];

    float v[8];
    float p;
    p  = cosf(x0.x + theta[0]);  v[0] = p;
    p *= cosf(x0.y + theta[1]);  v[1] = p;
    p *= cosf(x0.z + theta[2]);  v[2] = p;
    p *= cosf(x0.w + theta[3]);  v[3] = p;
    p *= cosf(x1.x + theta[4]);  v[4] = p;
    p *= cosf(x1.y + theta[5]);  v[5] = p;
    p *= cosf(x1.z + theta[6]);  v[6] = p;
    p *= cosf(x1.w + theta[7]);  v[7] = p;

    // sqrt(log2(e)/sqrt(8)) folded into BOTH score operands
    const float CLS = 0.71421430302f;   // sqrt(0.51010205144336435)
    uint32_t hw[4];
#pragma unroll
    for (int j = 0; j < 4; ++j) {
        __half h0 = __float2half_rn(v[2 * j] * CLS);
        __half h1 = __float2half_rn(v[2 * j + 1] * CLS);
        hw[j] = (uint32_t)__half_as_ushort(h0) | ((uint32_t)__half_as_ushort(h1) << 16);
    }
    ((uint4*)g_kh)[r] = make_uint4(hw[0], hw[1], hw[2], hw[3]);

    // pair-packed V with mask folded: g_vp[bh][s/2][n] = half2{v*m (even), (odd)}
    float m = (float)mask[b * NS + s];
    uint16_t* vp16 = (uint16_t*)g_vp;
    size_t base = (((size_t)bh * (NS / 2) + (s >> 1)) * 8) * 2 + (s & 1);
#pragma unroll
    for (int n = 0; n < 8; ++n)
        vp16[base + 2 * n] = __half_as_ushort(__float2half_rn(v[n] * m));
}

// ---------------------------------------------------------------------------
// Kernel B: HMMA flash attention. CTA = (head bh, 128-query tile), 8 warps.
// Per 16q x 16k iter: 3x LDS.64 + 2 score HMMA (k8, f16 acc) -> ex2.f16x2
//   -> PV HMMA + den HMMA (k16, f32 acc). No cvt, no FFMA epilogue.
// SMEM layouts are block-interleaved so each operand pair is one LDS.64.
// ---------------------------------------------------------------------------
__global__ void __launch_bounds__(256) attn_kernel(const int* __restrict__ mask) {
    extern __shared__ char smem[];
    uint32_t* sKh = (uint32_t*)smem;                    // 32 KB, [blk][r][cp][half]
    uint32_t* sVp = sKh + NS * 4;                       // 32 KB, [blk][n][cp][half]
    uint32_t* sVm = sVp + NS * 4;                       //  4 KB, [blk][cp][half]

    int tid = threadIdx.x;
    int bh = blockIdx.x;
    int b  = bh >> 4;
    int h  = bh & (NH - 1);

    {   // stage with block-interleaved re-layout
        const uint4* gh = (const uint4*)(g_kh + (size_t)bh * NS * 4);
        const uint4* gv = (const uint4*)(g_vp + (size_t)bh * (NS / 2) * 8);
        // K: key s -> blk=s>>4, row=s&7, half=(s>>3)&1; word cp at [blk*64 + row*8 + cp*2 + half]
        for (int s = tid; s < NS; s += 256) {
            uint4 k = gh[s];
            uint32_t* d = sKh + ((s >> 4) * 64 + (s & 7) * 8 + ((s >> 3) & 1));
            d[0] = k.x; d[2] = k.y; d[4] = k.z; d[6] = k.w;
        }
        // V: uint4 i -> pair p=i>>1, nb=(i&1)*4; dest [ (p>>3)*64 + (nb+j)*8 + (p&3)*2 + ((p>>2)&1) ]
        for (int i = tid; i < NS; i += 256) {
            uint4 v = gv[i];
            int p = i >> 1;
            uint32_t* d = sVp + ((p >> 3) * 64 + (i & 1) * 32 + (p & 3) * 2 + ((p >> 2) & 1));
            d[0] = v.x; d[8] = v.y; d[16] = v.z; d[24] = v.w;
        }
        // mask pairs: pair i -> [ (i>>3)*8 + (i&3)*2 + ((i>>2)&1) ]
        const int* mrow = mask + b * NS;
        for (int i = tid; i < NS / 2; i += 256) {
            __half m0 = __float2half_rn((float)mrow[2 * i]);
            __half m1 = __float2half_rn((float)mrow[2 * i + 1]);
            uint32_t pk = (uint32_t)__half_as_ushort(m0) | ((uint32_t)__half_as_ushort(m1) << 16);
            sVm[(i >> 3) * 8 + (i & 3) * 2 + ((i >> 2) & 1)] = pk;
        }
    }
    __syncthreads();

    int warp = tid >> 5, lane = tid & 31;
    int r0 = lane >> 2, cp = lane & 3;
    int qw = blockIdx.y * 128 + warp * 16;              // warp's first query

    // A fragment (16 queries x 8 dims), 2 regs, from GMEM once
    const uint32_t* gkh = g_kh + (size_t)bh * NS * 4;
    uint32_t A0 = gkh[(qw + r0) * 4 + cp];
    uint32_t A1 = gkh[(qw + r0 + 8) * 4 + cp];

    float o[4]  = {0.f, 0.f, 0.f, 0.f};     // PV accumulator
    float o2[4] = {0.f, 0.f, 0.f, 0.f};     // den accumulator

    const int off  = r0 * 8 + cp * 2;       // u32 offset within a 16-key block
    const int offm = cp * 2;

#pragma unroll 4
    for (int it = 0; it < NS / 16; ++it) {
        uint2 kk = *(const uint2*)(sKh + it * 64 + off);   // {bh0, bh1}
        uint2 vv = *(const uint2*)(sVp + it * 64 + off);   // {vb0, vb1}
        uint2 mm = *(const uint2*)(sVm + it * 8 + offm);   // {vm0, vm1}

        uint32_t d0l, d0h, d1l, d1h;
        mma16808h(d0l, d0h, A0, A1, kk.x);                 // keys 0-7 of block
        mma16808h(d1l, d1h, A0, A1, kk.y);                 // keys 8-15

        uint32_t pe0 = ex2h2(d0l);   // P frag a0: row r0,   k 2cp..2cp+1
        uint32_t pe1 = ex2h2(d0h);   //        a1: row r0+8
        uint32_t po0 = ex2h2(d1l);   //        a2: row r0,   k 8+2cp
        uint32_t po1 = ex2h2(d1h);   //        a3: row r0+8

        mma16816(o,  pe0, pe1, po0, po1, vv.x, vv.y);      // numerator
        mma16816(o2, pe0, pe1, po0, po1, mm.x, mm.y);      // denominator
    }

    // den reduced over keys by the MMA: row r0 -> o2[0], row r0+8 -> o2[2]
    float i0 = __fdividef(1.0f, fmaxf(o2[0], 1e-30f));
    float i1 = __fdividef(1.0f, fmaxf(o2[2], 1e-30f));

    size_t col = (size_t)h * ND + 2 * cp;
    float2* out0 = (float2*)(g_attn + ((size_t)(b * NS + qw + r0) * NE + col));
    float2* out1 = (float2*)(g_attn + ((size_t)(b * NS + qw + r0 + 8) * NE + col));
    *out0 = make_float2(o[0] * i0, o[1] * i0);
    *out1 = make_float2(o[2] * i1, o[3] * i1);
}

// ---------------------------------------------------------------------------
// Kernel C: out[r, e] = sum_f attn[r, f] * w_out[e, f]
// ---------------------------------------------------------------------------
__global__ void __launch_bounds__(256) out_kernel(const float* __restrict__ w,
                                                  float* __restrict__ out) {
    extern __shared__ float sW[];   // [128][132] padded transpose
    for (int i = threadIdx.x; i < NE * NE; i += 256) {
        int e = i >> 7;
        int f = i & 127;
        sW[f * 132 + e] = w[i];
    }
    __syncthreads();

    int warp = threadIdx.x >> 5;
    int lane = threadIdx.x & 31;
    int rbase = blockIdx.x * 64 + warp * 8;

    for (int k = 0; k < 8; ++k) {
        int r = rbase + k;
        const float4* arow = (const float4*)(g_attn + (size_t)r * NE);
        float4 acc = make_float4(0.f, 0.f, 0.f, 0.f);
#pragma unroll 4
        for (int fi = 0; fi < 32; ++fi) {
            float4 a4 = arow[fi];
            int f = fi * 4;
            float4 w0 = *(const float4*)&sW[(f + 0) * 132 + lane * 4];
            acc.x = fmaf(a4.x, w0.x, acc.x);
            acc.y = fmaf(a4.x, w0.y, acc.y);
            acc.z = fmaf(a4.x, w0.z, acc.z);
            acc.w = fmaf(a4.x, w0.w, acc.w);
            float4 w1 = *(const float4*)&sW[(f + 1) * 132 + lane * 4];
            acc.x = fmaf(a4.y, w1.x, acc.x);
            acc.y = fmaf(a4.y, w1.y, acc.y);
            acc.z = fmaf(a4.y, w1.z, acc.z);
            acc.w = fmaf(a4.y, w1.w, acc.w);
            float4 w2 = *(const float4*)&sW[(f + 2) * 132 + lane * 4];
            acc.x = fmaf(a4.z, w2.x, acc.x);
            acc.y = fmaf(a4.z, w2.y, acc.y);
            acc.z = fmaf(a4.z, w2.z, acc.z);
            acc.w = fmaf(a4.z, w2.w, acc.w);
            float4 w3 = *(const float4*)&sW[(f + 3) * 132 + lane * 4];
            acc.x = fmaf(a4.w, w3.x, acc.x);
            acc.y = fmaf(a4.w, w3.y, acc.y);
            acc.z = fmaf(a4.w, w3.z, acc.z);
            acc.w = fmaf(a4.w, w3.w, acc.w);
        }
        *(float4*)(out + (size_t)r * NE + lane * 4) = acc;
    }
}

// ---------------------------------------------------------------------------
extern "C" void kernel_launch(void* const* d_in, const int* in_sizes, int n_in,
                              void* d_out, int out_size) {
    const float* x     = (const float*)d_in[0];
    const float* theta = (const float*)d_in[1];
    const float* w     = (const float*)d_in[2];
    const int*   mask  = (const int*)d_in[3];
    float*       out   = (float*)d_out;

    qgen_kernel<<<(NBH * NS) / 128, 128>>>(x, theta, mask);

    int smB = NS * 4 * 4 * 2 + (NS / 2) * 4;   // 64 KB K/V + 4 KB mask = 69632 B
    cudaFuncSetAttribute(attn_kernel, cudaFuncAttributeMaxDynamicSharedMemorySize, smB);
    attn_kernel<<<dim3(NBH, NS / 128), 256, smB>>>(mask);

    int smC = 128 * 132 * 4;
    cudaFuncSetAttribute(out_kernel, cudaFuncAttributeMaxDynamicSharedMemorySize, smC);
    out_kernel<<<(NB * NS) / 64, 256, smC>>>(w, out);
}